// round 9
// baseline (speedup 1.0000x reference)
#include <cuda_runtime.h>
#include <cstdint>
#include <cstddef>

// ----------------------------------------------------------------------------
// InstanceSegmentationHead: fused level-assignment + per-level greedy NMS
// (K=64) in ONE kernel (6 blocks), then persistent work-stealing ROI align.
// B=2, C=256, N=2048 per source, feature sizes 28/56/112.
// ----------------------------------------------------------------------------

#define NBOX 6144
#define BATCH 2
#define CCH 256
#define KKEEP 64
#define OUTP 14
#define CPB 16              // channels per roi virtual block
#define NVB  (BATCH * 192 * (CCH / CPB))   // 6144 virtual roi blocks
#define ROI_BLOCKS 740      // persistent blocks (148 SMs x 5)

// ---------------- scratch (__device__ globals; no allocation) ---------------
__device__ int g_sel[6][KKEEP];
__device__ int g_vbctr;     // roi work-stealing counter; reset by nms kernel

// order-preserving float->uint mapping (monotonic)
__device__ __forceinline__ unsigned ford(float f) {
    unsigned u = __float_as_uint(f);
    return (u & 0x80000000u) ? ~u : (u | 0x80000000u);
}

// --------------------- stage 1: fused prep + greedy NMS ----------------------
// one block per (batch, level). Block scans all 6144 raw boxes, compacts its
// level into SMEM (key u64 + xyxy float4), then register-resident NMS.
#define NMS_BD 512
#define NMS_U  12        // 512*12 = 6144 = NBOX

__global__ void __launch_bounds__(NMS_BD, 1) nms_kernel(
    const float* __restrict__ b32, const float* __restrict__ b16,
    const float* __restrict__ b8,
    const float* __restrict__ s32, const float* __restrict__ s16,
    const float* __restrict__ s8) {
    extern __shared__ char smraw[];
    unsigned long long* skey = (unsigned long long*)smraw;           // 48KB
    float4* sbox = (float4*)(smraw + (size_t)NBOX * 8);              // 96KB

    __shared__ unsigned long long rk[16];
    __shared__ int                rp[16];
    __shared__ unsigned long long s_wk;
    __shared__ float4             s_wb;
    __shared__ int                s_n;

    int bl   = blockIdx.x;           // 0..5
    int b    = bl / 3;
    int ltgt = bl - b * 3 + 1;       // target level 1..3
    int tid  = threadIdx.x;

    // reset the roi work-stealing counter (stream-ordered before roi_kernel)
    if (bl == 0 && tid == 0) g_vbctr = 0;

    if (tid == 0) s_n = 0;
    __syncthreads();

    // ---- fused prep: scan all boxes, keep this level's ----
    for (int j = tid; j < NBOX; j += NMS_BD) {
        int src = j >> 11;           // 0,1,2
        int jj  = j & 2047;
        const float* bp; const float* sp; float s;
        if (src == 0)      { bp = b32; sp = s32; s = 32.f; }
        else if (src == 1) { bp = b16; sp = s16; s = 16.f; }
        else               { bp = b8;  sp = s8;  s = 8.f;  }
        const float4 bx = *(const float4*)(bp + ((size_t)(b * 2048 + jj)) * 4);
        float sc = sp[(size_t)b * 2048 + jj];

        // level from UNscaled size: clip(floor(3 + log2(sqrt(w*h)/224)), 1, 4)
        float sz = sqrtf(__fmul_rn(bx.z, bx.w));
        float lv = floorf(__fadd_rn(3.0f, log2f(__fdiv_rn(sz, 224.0f))));
        lv = fminf(fmaxf(lv, 1.0f), 4.0f);

        if ((int)lv == ltgt) {
            // scaled xyxy (single-op IEEE rounding, no fma contraction)
            float scx = __fmul_rn(bx.x, s), scy = __fmul_rn(bx.y, s);
            float sw  = __fmul_rn(bx.z, s), sh  = __fmul_rn(bx.w, s);
            float hx  = __fmul_rn(sw, 0.5f), hy = __fmul_rn(sh, 0.5f);
            float x1  = __fsub_rn(scx, hx), y1 = __fsub_rn(scy, hy);
            float x2  = __fadd_rn(scx, hx), y2 = __fadd_rn(scy, hy);
            int pos = atomicAdd(&s_n, 1);
            // key: higher score wins; ties -> smaller orig index (jnp.argmax)
            skey[pos] = ((unsigned long long)ford(sc) << 32) |
                        (unsigned long long)(0xFFFFFFFFu - (unsigned)j);
            sbox[pos] = make_float4(x1, y1, x2, y2);
        }
    }
    __syncthreads();
    int n = s_n;

    // ---- register-resident load ----
    unsigned long long key[NMS_U];
    float4             box[NMS_U];
    float              area[NMS_U];
    #pragma unroll
    for (int u = 0; u < NMS_U; ++u) {
        int j = tid + u * NMS_BD;
        key[u]  = 0ull;
        box[u]  = make_float4(0.f, 0.f, 0.f, 0.f);
        area[u] = 0.f;
        if (j < n) {
            key[u] = skey[j];
            float4 bb = sbox[j];
            box[u]  = bb;
            area[u] = __fmul_rn(fmaxf(__fsub_rn(bb.z, bb.x), 0.f),
                                fmaxf(__fsub_rn(bb.w, bb.y), 0.f));
        }
    }
    __syncthreads();

    const float MLO = 2.9802322387695312e-8f;    // 2^-25 = half-ulp of 0.7f

    // initial "winner" suppresses nothing (intersection clamps to 0)
    float4 wb = make_float4(1e30f, 1e30f, 1e30f, 1e30f);

    int it = 0;
    for (; it < KKEEP; ++it) {
        float a = __fmul_rn(fmaxf(__fsub_rn(wb.z, wb.x), 0.f),
                            fmaxf(__fsub_rn(wb.w, wb.y), 0.f));

        unsigned long long bk = 0ull;
        int bp = 0;

        #pragma unroll
        for (int u = 0; u < NMS_U; ++u) {
            if (u * NMS_BD >= n) break;          // uniform: skip unused tail
            float4 bb = box[u];
            float ix1 = fmaxf(wb.x, bb.x), iy1 = fmaxf(wb.y, bb.y);
            float ix2 = fminf(wb.z, bb.z), iy2 = fminf(wb.w, bb.w);
            float inter = __fmul_rn(fmaxf(__fsub_rn(ix2, ix1), 0.f),
                                    fmaxf(__fsub_rn(iy2, iy1), 0.f));
            float denom = __fadd_rn(__fsub_rn(__fadd_rn(a, area[u]), inter), 1e-9f);
            // suppress <=> rn(inter/denom) > 0.7f <=> inter >= (0.7f+2^-25)*denom
            float dd = __fmaf_rn(-0.7f, denom, inter);
            float tt = __fmul_rn(MLO, denom);    // exact (power of two)
            if (dd >= tt) key[u] = 0ull;         // dead keys can never win
            if (key[u] > bk) { bk = key[u]; bp = tid + u * NMS_BD; }
        }

        // block argmax of (key, pos)
        #pragma unroll
        for (int off = 16; off; off >>= 1) {
            unsigned long long ok = __shfl_down_sync(0xFFFFFFFFu, bk, off);
            int                op = __shfl_down_sync(0xFFFFFFFFu, bp, off);
            if (ok > bk) { bk = ok; bp = op; }
        }
        if ((tid & 31) == 0) { rk[tid >> 5] = bk; rp[tid >> 5] = bp; }
        __syncthreads();
        if (tid < 32) {
            bk = (tid < 16) ? rk[tid] : 0ull;
            bp = (tid < 16) ? rp[tid] : 0;
            #pragma unroll
            for (int off = 8; off; off >>= 1) {
                unsigned long long ok = __shfl_down_sync(0xFFFFFFFFu, bk, off);
                int                op = __shfl_down_sync(0xFFFFFFFFu, bp, off);
                if (ok > bk) { bk = ok; bp = op; }
            }
            if (tid == 0) { s_wk = bk; s_wb = sbox[bp]; }
        }
        __syncthreads();

        unsigned long long wk = s_wk;
        if (wk == 0ull) break;                   // all suppressed -> rest are -1
        wb = s_wb;
        if (tid == 0)
            g_sel[bl][it] = (int)(0xFFFFFFFFu - (unsigned)(wk & 0xFFFFFFFFull));
    }

    for (int j = it + tid; j < KKEEP; j += NMS_BD) g_sel[bl][j] = -1;
}

// ---------------------------- stage 2: ROI align -----------------------------
// Persistent work-stealing: 740 blocks pull virtual-block ids (0..6143) off a
// global counter. vb -> (bk = vb>>4 : one (b,k) tile, cg = (vb&15)*16 channels).
// Fast path: box fully right/below the map -> tile == F[c][S*S-1] exactly.
__global__ void __launch_bounds__(224, 5) roi_kernel(
    const float* __restrict__ p32, const float* __restrict__ p16,
    const float* __restrict__ p8,
    const float* __restrict__ b32, const float* __restrict__ b16,
    const float* __restrict__ b8,
    float* __restrict__ out) {
    __shared__ int s_vb;
    int tid = threadIdx.x;

    for (;;) {
        if (tid == 0) s_vb = atomicAdd(&g_vbctr, 1);
        __syncthreads();
        int vb = s_vb;
        __syncthreads();                // s_vb reusable next trip
        if (vb >= NVB) return;

        int bk  = vb >> 4;             // 0..383
        int b   = bk / 192;
        int k   = bk - b * 192;
        int lvl = k >> 6;              // 0,1,2
        int kk  = k & 63;
        int cg  = (vb & 15) * CPB;

        float* o = out + (size_t)bk * (CCH * OUTP * OUTP) + (size_t)cg * (OUTP * OUTP);
        float4* o4 = (float4*)o;       // 784B-aligned

        int sel = g_sel[b * 3 + lvl][kk];
        if (sel < 0) {
            float4 z = make_float4(0.f, 0.f, 0.f, 0.f);
            for (int i = tid; i < CPB * 49; i += 224) o4[i] = z;
            continue;
        }

        int S = (lvl == 0) ? 28 : (lvl == 1) ? 56 : 112;
        int SS = S * S;
        const float* fbase = ((lvl == 0) ? p32 : (lvl == 1) ? p16 : p8)
                             + ((size_t)b * CCH + cg) * (size_t)SS;

        // recompute the scaled cxcywh box from raw inputs (bit-exact vs the
        // reference's scaled concat); fed into roi_align as x1,y1,x2,y2.
        int src = sel >> 11;
        int jj  = sel & 2047;
        const float* bpp = ((src == 0) ? b32 : (src == 1) ? b16 : b8)
                           + ((size_t)(b * 2048 + jj)) * 4;
        float s = (src == 0) ? 32.f : (src == 1) ? 16.f : 8.f;
        float x1 = __fmul_rn(bpp[0], s);
        float y1 = __fmul_rn(bpp[1], s);
        float x2 = __fmul_rn(bpp[2], s);
        float y2 = __fmul_rn(bpp[3], s);
        float bw = __fdiv_rn(__fsub_rn(x2, x1), 14.0f);
        float bh = __fdiv_rn(__fsub_rn(y2, y1), 14.0f);

        // fast path: all samples clamp to the (S-1,S-1) corner.
        // 224 = CPB(16) * 14 -> full coverage: c in [0,16), r in [0,14)
        if (x1 >= (float)(S - 1) && y1 >= (float)(S - 1) && bw >= 0.f && bh >= 0.f) {
            int c = tid / 14;
            int r = tid - c * 14;
            float v = __ldg(fbase + (size_t)c * SS + (SS - 1));
            float4 v4 = make_float4(v, v, v, v);
            int base = c * 49;
            #pragma unroll
            for (int i = r; i < 49; i += 14) o4[base + i] = v4;
            continue;
        }

        if (tid < OUTP * OUTP) {       // 196 active threads
            int p  = tid;
            int oy = p / OUTP;
            int ox = p - oy * OUTP;
            float lim = (float)(S - 1);

            int   iy0[2], iy1[2], ix0[2], ix1[2];
            float fy[2], fx[2];
            #pragma unroll
            for (int q = 0; q < 2; ++q) {
                float ty = __fadd_rn((float)oy, q ? 0.75f : 0.25f);
                float cy = __fadd_rn(y1, __fmul_rn(ty, bh));
                cy = fminf(fmaxf(cy, 0.0f), lim);
                float c0 = floorf(cy);
                fy[q]  = __fsub_rn(cy, c0);
                iy0[q] = (int)c0;
                iy1[q] = min(iy0[q] + 1, S - 1);

                float tx = __fadd_rn((float)ox, q ? 0.75f : 0.25f);
                float cx = __fadd_rn(x1, __fmul_rn(tx, bw));
                cx = fminf(fmaxf(cx, 0.0f), lim);
                float d0 = floorf(cx);
                fx[q]  = __fsub_rn(cx, d0);
                ix0[q] = (int)d0;
                ix1[q] = min(ix0[q] + 1, S - 1);
            }

            // 16 corner offsets + weights (0.25 mean folded in)
            int   off[16];
            float w[16];
            #pragma unroll
            for (int sy = 0; sy < 2; ++sy) {
                #pragma unroll
                for (int sx = 0; sx < 2; ++sx) {
                    int s4 = (sy * 2 + sx) * 4;
                    int Y0 = iy0[sy] * S, Y1 = iy1[sy] * S;
                    float gy = fy[sy], igy = 1.0f - gy;
                    float gx = fx[sx], igx = 1.0f - gx;
                    off[s4 + 0] = Y0 + ix0[sx];  w[s4 + 0] = igy * igx * 0.25f;
                    off[s4 + 1] = Y0 + ix1[sx];  w[s4 + 1] = igy * gx  * 0.25f;
                    off[s4 + 2] = Y1 + ix0[sx];  w[s4 + 2] = gy  * igx * 0.25f;
                    off[s4 + 3] = Y1 + ix1[sx];  w[s4 + 3] = gy  * gx  * 0.25f;
                }
            }

            const float* f  = fbase;
            float*       op = o + p;
            #pragma unroll 2
            for (int c = 0; c < CPB; ++c) {
                float a0 = 0.f, a1 = 0.f, a2 = 0.f, a3 = 0.f;
                #pragma unroll
                for (int i = 0; i < 4; ++i) {
                    a0 = fmaf(__ldg(f + off[4 * i + 0]), w[4 * i + 0], a0);
                    a1 = fmaf(__ldg(f + off[4 * i + 1]), w[4 * i + 1], a1);
                    a2 = fmaf(__ldg(f + off[4 * i + 2]), w[4 * i + 2], a2);
                    a3 = fmaf(__ldg(f + off[4 * i + 3]), w[4 * i + 3], a3);
                }
                *op = (a0 + a1) + (a2 + a3);
                f  += SS;
                op += OUTP * OUTP;
            }
        }
    }
}

// ------------------------------- launcher ------------------------------------
extern "C" void kernel_launch(void* const* d_in, const int* in_sizes, int n_in,
                              void* d_out, int out_size) {
    const float* p32 = (const float*)d_in[0];
    const float* p16 = (const float*)d_in[1];
    const float* p8  = (const float*)d_in[2];
    // d_in[3] = p4 (unused by the reference forward)
    const float* b32 = (const float*)d_in[4];
    const float* b16 = (const float*)d_in[5];
    const float* b8  = (const float*)d_in[6];
    const float* s32 = (const float*)d_in[7];
    const float* s16 = (const float*)d_in[8];
    const float* s8  = (const float*)d_in[9];
    float* out = (float*)d_out;

    // keys (48KB) + boxes (96KB) = 144KB dynamic smem
    static const size_t NMS_SMEM = (size_t)NBOX * (8 + 16);
    cudaFuncSetAttribute(nms_kernel, cudaFuncAttributeMaxDynamicSharedMemorySize,
                         (int)NMS_SMEM);

    nms_kernel<<<6, NMS_BD, NMS_SMEM>>>(b32, b16, b8, s32, s16, s8);
    roi_kernel<<<ROI_BLOCKS, 224>>>(p32, p16, p8, b32, b16, b8, out);
}

// round 10
// speedup vs baseline: 1.3889x; 1.3889x over previous
#include <cuda_runtime.h>
#include <cstdint>
#include <cstddef>

// ----------------------------------------------------------------------------
// InstanceSegmentationHead, pipelined by level:
//   3 graph branches: nms(level L) -> roi(level L),  L in {1,2,3}.
// nms levels cost ~8/30/50us (n ~ 500/2100/3400); roi for small levels runs
// concurrently with the big level's nms -> critical path = nms_L3 + roi_L3.
// B=2, C=256, N=2048 per source, feature sizes 28/56/112.
// ----------------------------------------------------------------------------

#define NBOX 6144
#define BATCH 2
#define CCH 256
#define KKEEP 64
#define OUTP 14
#define CPB 16              // channels per roi block

// ---------------- scratch (__device__ globals; no allocation) ---------------
__device__ int g_sel[6][KKEEP];

// order-preserving float->uint mapping (monotonic)
__device__ __forceinline__ unsigned ford(float f) {
    unsigned u = __float_as_uint(f);
    return (u & 0x80000000u) ? ~u : (u | 0x80000000u);
}

// --------------------- fused prep + greedy NMS (one level) -------------------
// grid = 2 blocks (one per batch). Block scans all 6144 raw boxes, compacts its
// level into SMEM (key u64 + xyxy float4), then register-resident NMS.
// key = ford(score)<<26 | (8191-j)<<13 | slot  — argmax carries ONE u64;
// winner box recovered from the slot bits.
#define NMS_BD 512
#define NMS_U  12        // 512*12 = 6144 = NBOX

__global__ void __launch_bounds__(NMS_BD, 1) nms_kernel(
    const float* __restrict__ b32, const float* __restrict__ b16,
    const float* __restrict__ b8,
    const float* __restrict__ s32, const float* __restrict__ s16,
    const float* __restrict__ s8, int ltgt) {
    extern __shared__ char smraw[];
    unsigned long long* skey = (unsigned long long*)smraw;           // 48KB
    float4* sbox = (float4*)(smraw + (size_t)NBOX * 8);              // 96KB

    __shared__ unsigned long long rk[16];
    __shared__ unsigned long long s_wk;
    __shared__ int                s_n;

    int b    = blockIdx.x;           // batch
    int bl   = b * 3 + (ltgt - 1);   // g_sel row
    int tid  = threadIdx.x;
    int lane = tid & 31;

    if (tid == 0) s_n = 0;
    __syncthreads();

    // ---- fused prep: scan all boxes, keep this level's ----
    for (int j = tid; j < NBOX; j += NMS_BD) {
        int src = j >> 11;           // 0,1,2
        int jj  = j & 2047;
        const float* bp; const float* sp; float s;
        if (src == 0)      { bp = b32; sp = s32; s = 32.f; }
        else if (src == 1) { bp = b16; sp = s16; s = 16.f; }
        else               { bp = b8;  sp = s8;  s = 8.f;  }
        const float4 bx = *(const float4*)(bp + ((size_t)(b * 2048 + jj)) * 4);
        float sc = sp[(size_t)b * 2048 + jj];

        // level from UNscaled size: clip(floor(3 + log2(sqrt(w*h)/224)), 1, 4)
        float sz = sqrtf(__fmul_rn(bx.z, bx.w));
        float lv = floorf(__fadd_rn(3.0f, log2f(__fdiv_rn(sz, 224.0f))));
        lv = fminf(fmaxf(lv, 1.0f), 4.0f);

        if ((int)lv == ltgt) {
            // scaled xyxy (single-op IEEE rounding, no fma contraction)
            float scx = __fmul_rn(bx.x, s), scy = __fmul_rn(bx.y, s);
            float sw  = __fmul_rn(bx.z, s), sh  = __fmul_rn(bx.w, s);
            float hx  = __fmul_rn(sw, 0.5f), hy = __fmul_rn(sh, 0.5f);
            float x1  = __fsub_rn(scx, hx), y1 = __fsub_rn(scy, hy);
            float x2  = __fadd_rn(scx, hx), y2 = __fadd_rn(scy, hy);
            int pos = atomicAdd(&s_n, 1);
            // higher score wins; ties -> smaller orig index; low bits = slot
            skey[pos] = ((unsigned long long)ford(sc) << 26) |
                        ((unsigned long long)(8191 - j) << 13) |
                        (unsigned long long)pos;
            sbox[pos] = make_float4(x1, y1, x2, y2);
        }
    }
    __syncthreads();
    int n = s_n;

    // ---- register-resident load ----
    unsigned long long key[NMS_U];
    float4             box[NMS_U];
    float              area[NMS_U];
    #pragma unroll
    for (int u = 0; u < NMS_U; ++u) {
        int j = tid + u * NMS_BD;
        key[u]  = 0ull;
        box[u]  = make_float4(0.f, 0.f, 0.f, 0.f);
        area[u] = 0.f;
        if (j < n) {
            key[u] = skey[j];
            float4 bb = sbox[j];
            box[u]  = bb;
            area[u] = __fmul_rn(fmaxf(__fsub_rn(bb.z, bb.x), 0.f),
                                fmaxf(__fsub_rn(bb.w, bb.y), 0.f));
        }
    }
    __syncthreads();

    const float MLO = 2.9802322387695312e-8f;    // 2^-25 = half-ulp of 0.7f

    // initial "winner" suppresses nothing (intersection clamps to 0)
    float4 wb = make_float4(1e30f, 1e30f, 1e30f, 1e30f);

    int it = 0;
    for (; it < KKEEP; ++it) {
        float a = __fmul_rn(fmaxf(__fsub_rn(wb.z, wb.x), 0.f),
                            fmaxf(__fsub_rn(wb.w, wb.y), 0.f));

        unsigned long long bk = 0ull;

        #pragma unroll
        for (int u = 0; u < NMS_U; ++u) {
            if (u * NMS_BD >= n) break;          // uniform: skip unused tail
            float4 bb = box[u];
            float ix1 = fmaxf(wb.x, bb.x), iy1 = fmaxf(wb.y, bb.y);
            float ix2 = fminf(wb.z, bb.z), iy2 = fminf(wb.w, bb.w);
            float inter = __fmul_rn(fmaxf(__fsub_rn(ix2, ix1), 0.f),
                                    fmaxf(__fsub_rn(iy2, iy1), 0.f));
            float denom = __fadd_rn(__fsub_rn(__fadd_rn(a, area[u]), inter), 1e-9f);
            // suppress <=> rn(inter/denom) > 0.7f <=> inter >= (0.7f+2^-25)*denom
            float dd = __fmaf_rn(-0.7f, denom, inter);
            float tt = __fmul_rn(MLO, denom);    // exact (power of two)
            if (dd >= tt) key[u] = 0ull;         // dead keys can never win
            if (key[u] > bk) bk = key[u];
        }

        // block argmax of key (u64 only)
        #pragma unroll
        for (int off = 16; off; off >>= 1) {
            unsigned long long ok = __shfl_down_sync(0xFFFFFFFFu, bk, off);
            if (ok > bk) bk = ok;
        }
        if (lane == 0) rk[tid >> 5] = bk;
        __syncthreads();
        if (tid < 32) {
            bk = (lane < 16) ? rk[lane] : 0ull;
            #pragma unroll
            for (int off = 8; off; off >>= 1) {
                unsigned long long ok = __shfl_down_sync(0xFFFFFFFFu, bk, off);
                if (ok > bk) bk = ok;
            }
            if (tid == 0) s_wk = bk;
        }
        __syncthreads();

        unsigned long long wk = s_wk;
        if (wk == 0ull) break;                   // all suppressed -> rest are -1
        wb = sbox[(int)(wk & 8191u)];            // broadcast LDS
        if (tid == 0)
            g_sel[bl][it] = 8191 - (int)((wk >> 13) & 8191u);
    }

    for (int j = it + tid; j < KKEEP; j += NMS_BD) g_sel[bl][j] = -1;
}

// ------------------------------ ROI align (one level) ------------------------
// grid.x = B*64 (b = x>>6, kk = x&63), grid.y = 16 channel groups of CPB=16.
// 224 threads. Fast path: box fully right/below map -> tile == F[c][S*S-1].
__global__ void __launch_bounds__(224, 4) roi_kernel(
    const float* __restrict__ feat,
    const float* __restrict__ b32, const float* __restrict__ b16,
    const float* __restrict__ b8,
    float* __restrict__ out, int lvl, int S) {
    int b   = blockIdx.x >> 6;
    int kk  = blockIdx.x & 63;
    int k   = lvl * 64 + kk;
    int cg  = blockIdx.y * CPB;
    int tid = threadIdx.x;

    float* o = out + ((size_t)(b * 192 + k)) * (CCH * OUTP * OUTP)
                   + (size_t)cg * (OUTP * OUTP);
    float4* o4 = (float4*)o;       // 784B-aligned

    int sel = g_sel[b * 3 + lvl][kk];
    if (sel < 0) {
        float4 z = make_float4(0.f, 0.f, 0.f, 0.f);
        for (int i = tid; i < CPB * 49; i += 224) o4[i] = z;
        return;
    }

    int SS = S * S;
    const float* fbase = feat + ((size_t)b * CCH + cg) * (size_t)SS;

    // recompute the scaled cxcywh box from raw inputs (bit-exact vs the
    // reference's scaled concat); fed into roi_align as x1,y1,x2,y2.
    int src = sel >> 11;
    int jj  = sel & 2047;
    const float* bpp = ((src == 0) ? b32 : (src == 1) ? b16 : b8)
                       + ((size_t)(b * 2048 + jj)) * 4;
    float s = (src == 0) ? 32.f : (src == 1) ? 16.f : 8.f;
    float x1 = __fmul_rn(bpp[0], s);
    float y1 = __fmul_rn(bpp[1], s);
    float x2 = __fmul_rn(bpp[2], s);
    float y2 = __fmul_rn(bpp[3], s);
    float bw = __fdiv_rn(__fsub_rn(x2, x1), 14.0f);
    float bh = __fdiv_rn(__fsub_rn(y2, y1), 14.0f);

    // fast path: all samples clamp to the (S-1,S-1) corner.
    // 224 = CPB(16) * 14 -> full coverage: c in [0,16), r in [0,14)
    if (x1 >= (float)(S - 1) && y1 >= (float)(S - 1) && bw >= 0.f && bh >= 0.f) {
        int c = tid / 14;
        int r = tid - c * 14;
        float v = __ldg(fbase + (size_t)c * SS + (SS - 1));
        float4 v4 = make_float4(v, v, v, v);
        int base = c * 49;
        #pragma unroll
        for (int i = r; i < 49; i += 14) o4[base + i] = v4;
        return;
    }

    if (tid >= OUTP * OUTP) return;             // 196 active threads

    int p  = tid;
    int oy = p / OUTP;
    int ox = p - oy * OUTP;
    float lim = (float)(S - 1);

    int   iy0[2], iy1[2], ix0[2], ix1[2];
    float fy[2], fx[2];
    #pragma unroll
    for (int q = 0; q < 2; ++q) {
        float ty = __fadd_rn((float)oy, q ? 0.75f : 0.25f);
        float cy = __fadd_rn(y1, __fmul_rn(ty, bh));
        cy = fminf(fmaxf(cy, 0.0f), lim);
        float c0 = floorf(cy);
        fy[q]  = __fsub_rn(cy, c0);
        iy0[q] = (int)c0;
        iy1[q] = min(iy0[q] + 1, S - 1);

        float tx = __fadd_rn((float)ox, q ? 0.75f : 0.25f);
        float cx = __fadd_rn(x1, __fmul_rn(tx, bw));
        cx = fminf(fmaxf(cx, 0.0f), lim);
        float d0 = floorf(cx);
        fx[q]  = __fsub_rn(cx, d0);
        ix0[q] = (int)d0;
        ix1[q] = min(ix0[q] + 1, S - 1);
    }

    // 16 corner offsets + weights (0.25 mean folded in)
    int   off[16];
    float w[16];
    #pragma unroll
    for (int sy = 0; sy < 2; ++sy) {
        #pragma unroll
        for (int sx = 0; sx < 2; ++sx) {
            int s4 = (sy * 2 + sx) * 4;
            int Y0 = iy0[sy] * S, Y1 = iy1[sy] * S;
            float gy = fy[sy], igy = 1.0f - gy;
            float gx = fx[sx], igx = 1.0f - gx;
            off[s4 + 0] = Y0 + ix0[sx];  w[s4 + 0] = igy * igx * 0.25f;
            off[s4 + 1] = Y0 + ix1[sx];  w[s4 + 1] = igy * gx  * 0.25f;
            off[s4 + 2] = Y1 + ix0[sx];  w[s4 + 2] = gy  * igx * 0.25f;
            off[s4 + 3] = Y1 + ix1[sx];  w[s4 + 3] = gy  * gx  * 0.25f;
        }
    }

    const float* f  = fbase;
    float*       op = o + p;
    #pragma unroll 2
    for (int c = 0; c < CPB; ++c) {
        float a0 = 0.f, a1 = 0.f, a2 = 0.f, a3 = 0.f;
        #pragma unroll
        for (int i = 0; i < 4; ++i) {
            a0 = fmaf(__ldg(f + off[4 * i + 0]), w[4 * i + 0], a0);
            a1 = fmaf(__ldg(f + off[4 * i + 1]), w[4 * i + 1], a1);
            a2 = fmaf(__ldg(f + off[4 * i + 2]), w[4 * i + 2], a2);
            a3 = fmaf(__ldg(f + off[4 * i + 3]), w[4 * i + 3], a3);
        }
        *op = (a0 + a1) + (a2 + a3);
        f  += SS;
        op += OUTP * OUTP;
    }
}

// ------------------------------- launcher ------------------------------------
extern "C" void kernel_launch(void* const* d_in, const int* in_sizes, int n_in,
                              void* d_out, int out_size) {
    const float* p32 = (const float*)d_in[0];
    const float* p16 = (const float*)d_in[1];
    const float* p8  = (const float*)d_in[2];
    // d_in[3] = p4 (unused by the reference forward)
    const float* b32 = (const float*)d_in[4];
    const float* b16 = (const float*)d_in[5];
    const float* b8  = (const float*)d_in[6];
    const float* s32 = (const float*)d_in[7];
    const float* s16 = (const float*)d_in[8];
    const float* s8  = (const float*)d_in[9];
    float* out = (float*)d_out;

    // side streams + fork/join events: created ONCE on the first (uncaptured)
    // correctness call; later captured calls record a 3-branch DAG.
    static cudaStream_t st1 = nullptr, st2 = nullptr;
    static cudaEvent_t  ev0, ev1, ev2;
    if (st1 == nullptr) {
        cudaStreamCreateWithFlags(&st1, cudaStreamNonBlocking);
        cudaStreamCreateWithFlags(&st2, cudaStreamNonBlocking);
        cudaEventCreateWithFlags(&ev0, cudaEventDisableTiming);
        cudaEventCreateWithFlags(&ev1, cudaEventDisableTiming);
        cudaEventCreateWithFlags(&ev2, cudaEventDisableTiming);
        // keys (48KB) + boxes (96KB) = 144KB dynamic smem
        cudaFuncSetAttribute(nms_kernel,
                             cudaFuncAttributeMaxDynamicSharedMemorySize,
                             (int)((size_t)NBOX * (8 + 16)));
    }
    const size_t NMS_SMEM = (size_t)NBOX * (8 + 16);

    // fork
    cudaEventRecord(ev0, 0);
    cudaStreamWaitEvent(st1, ev0, 0);
    cudaStreamWaitEvent(st2, ev0, 0);

    // branch 0 (default stream): level 3 — the long pole, launched first
    nms_kernel<<<2, NMS_BD, NMS_SMEM, 0>>>(b32, b16, b8, s32, s16, s8, 3);
    // branch 1: level 1
    nms_kernel<<<2, NMS_BD, NMS_SMEM, st1>>>(b32, b16, b8, s32, s16, s8, 1);
    // branch 2: level 2
    nms_kernel<<<2, NMS_BD, NMS_SMEM, st2>>>(b32, b16, b8, s32, s16, s8, 2);

    dim3 rg(BATCH * 64, CCH / CPB);
    roi_kernel<<<rg, 224, 0, st1>>>(p32, b32, b16, b8, out, 0, 28);
    roi_kernel<<<rg, 224, 0, st2>>>(p16, b32, b16, b8, out, 1, 56);
    roi_kernel<<<rg, 224, 0, 0  >>>(p8,  b32, b16, b8, out, 2, 112);

    // join
    cudaEventRecord(ev1, st1);
    cudaEventRecord(ev2, st2);
    cudaStreamWaitEvent(0, ev1, 0);
    cudaStreamWaitEvent(0, ev2, 0);
}

// round 11
// speedup vs baseline: 1.5378x; 1.1073x over previous
#include <cuda_runtime.h>
#include <cstdint>
#include <cstddef>

// ----------------------------------------------------------------------------
// InstanceSegmentationHead, pipelined by level:
//   3 graph branches: nms(level L) -> roi(level L),  L in {1,2,3}.
// roi has 4 paths: corner-clamped (1 load/ch), x-clamped / y-clamped
// (row/col constant, 56 loads/ch), and full bilinear.
// B=2, C=256, N=2048 per source, feature sizes 28/56/112.
// ----------------------------------------------------------------------------

#define NBOX 6144
#define BATCH 2
#define CCH 256
#define KKEEP 64
#define OUTP 14
#define CPB 16              // channels per roi block

// ---------------- scratch (__device__ globals; no allocation) ---------------
__device__ int g_sel[6][KKEEP];

// order-preserving float->uint mapping (monotonic)
__device__ __forceinline__ unsigned ford(float f) {
    unsigned u = __float_as_uint(f);
    return (u & 0x80000000u) ? ~u : (u | 0x80000000u);
}

// --------------------- fused prep + greedy NMS (one level) -------------------
// grid = 2 blocks (one per batch). Block scans all 6144 raw boxes, compacts its
// level into SMEM (key u64 + xyxy float4), then register-resident NMS.
// key = ford(score)<<26 | (8191-j)<<13 | slot  — argmax carries ONE u64;
// winner box recovered from the slot bits.
#define NMS_BD 512
#define NMS_U  12        // 512*12 = 6144 = NBOX

__global__ void __launch_bounds__(NMS_BD, 1) nms_kernel(
    const float* __restrict__ b32, const float* __restrict__ b16,
    const float* __restrict__ b8,
    const float* __restrict__ s32, const float* __restrict__ s16,
    const float* __restrict__ s8, int ltgt) {
    extern __shared__ char smraw[];
    unsigned long long* skey = (unsigned long long*)smraw;           // 48KB
    float4* sbox = (float4*)(smraw + (size_t)NBOX * 8);              // 96KB

    __shared__ unsigned long long rk[16];
    __shared__ unsigned long long s_wk;
    __shared__ int                s_n;

    int b    = blockIdx.x;           // batch
    int bl   = b * 3 + (ltgt - 1);   // g_sel row
    int tid  = threadIdx.x;
    int lane = tid & 31;

    if (tid == 0) s_n = 0;
    __syncthreads();

    // ---- fused prep: scan all boxes, keep this level's ----
    for (int j = tid; j < NBOX; j += NMS_BD) {
        int src = j >> 11;           // 0,1,2
        int jj  = j & 2047;
        const float* bp; const float* sp; float s;
        if (src == 0)      { bp = b32; sp = s32; s = 32.f; }
        else if (src == 1) { bp = b16; sp = s16; s = 16.f; }
        else               { bp = b8;  sp = s8;  s = 8.f;  }
        const float4 bx = *(const float4*)(bp + ((size_t)(b * 2048 + jj)) * 4);
        float sc = sp[(size_t)b * 2048 + jj];

        // level from UNscaled size: clip(floor(3 + log2(sqrt(w*h)/224)), 1, 4)
        float sz = sqrtf(__fmul_rn(bx.z, bx.w));
        float lv = floorf(__fadd_rn(3.0f, log2f(__fdiv_rn(sz, 224.0f))));
        lv = fminf(fmaxf(lv, 1.0f), 4.0f);

        if ((int)lv == ltgt) {
            // scaled xyxy (single-op IEEE rounding, no fma contraction)
            float scx = __fmul_rn(bx.x, s), scy = __fmul_rn(bx.y, s);
            float sw  = __fmul_rn(bx.z, s), sh  = __fmul_rn(bx.w, s);
            float hx  = __fmul_rn(sw, 0.5f), hy = __fmul_rn(sh, 0.5f);
            float x1  = __fsub_rn(scx, hx), y1 = __fsub_rn(scy, hy);
            float x2  = __fadd_rn(scx, hx), y2 = __fadd_rn(scy, hy);
            int pos = atomicAdd(&s_n, 1);
            // higher score wins; ties -> smaller orig index; low bits = slot
            skey[pos] = ((unsigned long long)ford(sc) << 26) |
                        ((unsigned long long)(8191 - j) << 13) |
                        (unsigned long long)pos;
            sbox[pos] = make_float4(x1, y1, x2, y2);
        }
    }
    __syncthreads();
    int n = s_n;

    // ---- register-resident load ----
    unsigned long long key[NMS_U];
    float4             box[NMS_U];
    float              area[NMS_U];
    #pragma unroll
    for (int u = 0; u < NMS_U; ++u) {
        int j = tid + u * NMS_BD;
        key[u]  = 0ull;
        box[u]  = make_float4(0.f, 0.f, 0.f, 0.f);
        area[u] = 0.f;
        if (j < n) {
            key[u] = skey[j];
            float4 bb = sbox[j];
            box[u]  = bb;
            area[u] = __fmul_rn(fmaxf(__fsub_rn(bb.z, bb.x), 0.f),
                                fmaxf(__fsub_rn(bb.w, bb.y), 0.f));
        }
    }
    __syncthreads();

    const float MLO = 2.9802322387695312e-8f;    // 2^-25 = half-ulp of 0.7f

    // initial "winner" suppresses nothing (intersection clamps to 0)
    float4 wb = make_float4(1e30f, 1e30f, 1e30f, 1e30f);

    int it = 0;
    for (; it < KKEEP; ++it) {
        float a = __fmul_rn(fmaxf(__fsub_rn(wb.z, wb.x), 0.f),
                            fmaxf(__fsub_rn(wb.w, wb.y), 0.f));

        unsigned long long bk = 0ull;

        #pragma unroll
        for (int u = 0; u < NMS_U; ++u) {
            if (u * NMS_BD >= n) break;          // uniform: skip unused tail
            float4 bb = box[u];
            float ix1 = fmaxf(wb.x, bb.x), iy1 = fmaxf(wb.y, bb.y);
            float ix2 = fminf(wb.z, bb.z), iy2 = fminf(wb.w, bb.w);
            float inter = __fmul_rn(fmaxf(__fsub_rn(ix2, ix1), 0.f),
                                    fmaxf(__fsub_rn(iy2, iy1), 0.f));
            float denom = __fadd_rn(__fsub_rn(__fadd_rn(a, area[u]), inter), 1e-9f);
            // suppress <=> rn(inter/denom) > 0.7f <=> inter >= (0.7f+2^-25)*denom
            float dd = __fmaf_rn(-0.7f, denom, inter);
            float tt = __fmul_rn(MLO, denom);    // exact (power of two)
            if (dd >= tt) key[u] = 0ull;         // dead keys can never win
            if (key[u] > bk) bk = key[u];
        }

        // block argmax of key (u64 only)
        #pragma unroll
        for (int off = 16; off; off >>= 1) {
            unsigned long long ok = __shfl_down_sync(0xFFFFFFFFu, bk, off);
            if (ok > bk) bk = ok;
        }
        if (lane == 0) rk[tid >> 5] = bk;
        __syncthreads();
        if (tid < 32) {
            bk = (lane < 16) ? rk[lane] : 0ull;
            #pragma unroll
            for (int off = 8; off; off >>= 1) {
                unsigned long long ok = __shfl_down_sync(0xFFFFFFFFu, bk, off);
                if (ok > bk) bk = ok;
            }
            if (tid == 0) s_wk = bk;
        }
        __syncthreads();

        unsigned long long wk = s_wk;
        if (wk == 0ull) break;                   // all suppressed -> rest are -1
        wb = sbox[(int)(wk & 8191u)];            // broadcast LDS
        if (tid == 0)
            g_sel[bl][it] = 8191 - (int)((wk >> 13) & 8191u);
    }

    for (int j = it + tid; j < KKEEP; j += NMS_BD) g_sel[bl][j] = -1;
}

// ------------------------------ ROI align (one level) ------------------------
// grid.x = B*64 (b = x>>6, kk = x&63), grid.y = 16 channel groups of CPB=16.
// 224 threads. Paths: corner-clamped / x-clamped / y-clamped / full bilinear.
__global__ void __launch_bounds__(224, 4) roi_kernel(
    const float* __restrict__ feat,
    const float* __restrict__ b32, const float* __restrict__ b16,
    const float* __restrict__ b8,
    float* __restrict__ out, int lvl, int S) {
    int b   = blockIdx.x >> 6;
    int kk  = blockIdx.x & 63;
    int k   = lvl * 64 + kk;
    int cg  = blockIdx.y * CPB;
    int tid = threadIdx.x;

    float* o = out + ((size_t)(b * 192 + k)) * (CCH * OUTP * OUTP)
                   + (size_t)cg * (OUTP * OUTP);
    float4* o4 = (float4*)o;       // 784B-aligned

    int sel = g_sel[b * 3 + lvl][kk];
    if (sel < 0) {
        float4 z = make_float4(0.f, 0.f, 0.f, 0.f);
        for (int i = tid; i < CPB * 49; i += 224) o4[i] = z;
        return;
    }

    int SS = S * S;
    const float* fbase = feat + ((size_t)b * CCH + cg) * (size_t)SS;

    // recompute the scaled cxcywh box from raw inputs (bit-exact vs the
    // reference's scaled concat); fed into roi_align as x1,y1,x2,y2.
    int src = sel >> 11;
    int jj  = sel & 2047;
    const float* bpp = ((src == 0) ? b32 : (src == 1) ? b16 : b8)
                       + ((size_t)(b * 2048 + jj)) * 4;
    float s = (src == 0) ? 32.f : (src == 1) ? 16.f : 8.f;
    float x1 = __fmul_rn(bpp[0], s);
    float y1 = __fmul_rn(bpp[1], s);
    float x2 = __fmul_rn(bpp[2], s);
    float y2 = __fmul_rn(bpp[3], s);
    float bw = __fdiv_rn(__fsub_rn(x2, x1), 14.0f);
    float bh = __fdiv_rn(__fsub_rn(y2, y1), 14.0f);

    float lim = (float)(S - 1);
    bool xc = (x1 >= lim) && (bw >= 0.f);   // all x-samples clamp to S-1, fx=0
    bool yc = (y1 >= lim) && (bh >= 0.f);   // all y-samples clamp to S-1, fy=0

    // ---- corner path: tile == F[c][S*S-1] exactly ----
    if (xc && yc) {
        int c = tid / 14;                 // 224 = 16*14: c in [0,16), r in [0,14)
        int r = tid - c * 14;
        float v = __ldg(fbase + (size_t)c * SS + (SS - 1));
        float4 v4 = make_float4(v, v, v, v);
        int base = c * 49;
        #pragma unroll
        for (int i = r; i < 49; i += 14) o4[base + i] = v4;
        return;
    }

    // ---- x-clamped: every row constant; v depends on (c, oy) only ----
    if (xc) {
        int c  = tid / 14;
        int oy = tid - c * 14;
        const float* f = fbase + (size_t)c * SS;
        float acc = 0.f;
        #pragma unroll
        for (int q = 0; q < 2; ++q) {
            float ty = __fadd_rn((float)oy, q ? 0.75f : 0.25f);
            float cy = __fadd_rn(y1, __fmul_rn(ty, bh));
            cy = fminf(fmaxf(cy, 0.0f), lim);
            float c0 = floorf(cy);
            float fy = __fsub_rn(cy, c0);
            int iy0 = (int)c0;
            int iy1 = min(iy0 + 1, S - 1);
            float g0 = __ldg(f + iy0 * S + (S - 1));
            float g1 = __ldg(f + iy1 * S + (S - 1));
            acc += g0 * (1.0f - fy) + g1 * fy;
        }
        float v = acc * 0.5f;             // mean of 4 samples, pairs equal
        float* op = o + c * 196 + oy * 14;
        #pragma unroll
        for (int i = 0; i < 14; ++i) op[i] = v;
        return;
    }

    // ---- y-clamped: every column constant; v depends on (c, ox) only ----
    if (yc) {
        int c  = tid / 14;
        int ox = tid - c * 14;
        const float* f = fbase + (size_t)c * SS + (size_t)(S - 1) * S;  // last row
        float acc = 0.f;
        #pragma unroll
        for (int q = 0; q < 2; ++q) {
            float tx = __fadd_rn((float)ox, q ? 0.75f : 0.25f);
            float cx = __fadd_rn(x1, __fmul_rn(tx, bw));
            cx = fminf(fmaxf(cx, 0.0f), lim);
            float d0 = floorf(cx);
            float fx = __fsub_rn(cx, d0);
            int ix0 = (int)d0;
            int ix1 = min(ix0 + 1, S - 1);
            float g0 = __ldg(f + ix0);
            float g1 = __ldg(f + ix1);
            acc += g0 * (1.0f - fx) + g1 * fx;
        }
        float v = acc * 0.5f;
        float* op = o + c * 196 + ox;
        #pragma unroll
        for (int i = 0; i < 14; ++i) op[i * 14] = v;
        return;
    }

    // ---- full bilinear path ----
    if (tid >= OUTP * OUTP) return;             // 196 active threads

    int p  = tid;
    int oy = p / OUTP;
    int ox = p - oy * OUTP;

    int   iy0[2], iy1[2], ix0[2], ix1[2];
    float fy[2], fx[2];
    #pragma unroll
    for (int q = 0; q < 2; ++q) {
        float ty = __fadd_rn((float)oy, q ? 0.75f : 0.25f);
        float cy = __fadd_rn(y1, __fmul_rn(ty, bh));
        cy = fminf(fmaxf(cy, 0.0f), lim);
        float c0 = floorf(cy);
        fy[q]  = __fsub_rn(cy, c0);
        iy0[q] = (int)c0;
        iy1[q] = min(iy0[q] + 1, S - 1);

        float tx = __fadd_rn((float)ox, q ? 0.75f : 0.25f);
        float cx = __fadd_rn(x1, __fmul_rn(tx, bw));
        cx = fminf(fmaxf(cx, 0.0f), lim);
        float d0 = floorf(cx);
        fx[q]  = __fsub_rn(cx, d0);
        ix0[q] = (int)d0;
        ix1[q] = min(ix0[q] + 1, S - 1);
    }

    // 16 corner offsets + weights (0.25 mean folded in)
    int   off[16];
    float w[16];
    #pragma unroll
    for (int sy = 0; sy < 2; ++sy) {
        #pragma unroll
        for (int sx = 0; sx < 2; ++sx) {
            int s4 = (sy * 2 + sx) * 4;
            int Y0 = iy0[sy] * S, Y1 = iy1[sy] * S;
            float gy = fy[sy], igy = 1.0f - gy;
            float gx = fx[sx], igx = 1.0f - gx;
            off[s4 + 0] = Y0 + ix0[sx];  w[s4 + 0] = igy * igx * 0.25f;
            off[s4 + 1] = Y0 + ix1[sx];  w[s4 + 1] = igy * gx  * 0.25f;
            off[s4 + 2] = Y1 + ix0[sx];  w[s4 + 2] = gy  * igx * 0.25f;
            off[s4 + 3] = Y1 + ix1[sx];  w[s4 + 3] = gy  * gx  * 0.25f;
        }
    }

    const float* f  = fbase;
    float*       op = o + p;
    #pragma unroll 2
    for (int c = 0; c < CPB; ++c) {
        float a0 = 0.f, a1 = 0.f, a2 = 0.f, a3 = 0.f;
        #pragma unroll
        for (int i = 0; i < 4; ++i) {
            a0 = fmaf(__ldg(f + off[4 * i + 0]), w[4 * i + 0], a0);
            a1 = fmaf(__ldg(f + off[4 * i + 1]), w[4 * i + 1], a1);
            a2 = fmaf(__ldg(f + off[4 * i + 2]), w[4 * i + 2], a2);
            a3 = fmaf(__ldg(f + off[4 * i + 3]), w[4 * i + 3], a3);
        }
        *op = (a0 + a1) + (a2 + a3);
        f  += SS;
        op += OUTP * OUTP;
    }
}

// ------------------------------- launcher ------------------------------------
extern "C" void kernel_launch(void* const* d_in, const int* in_sizes, int n_in,
                              void* d_out, int out_size) {
    const float* p32 = (const float*)d_in[0];
    const float* p16 = (const float*)d_in[1];
    const float* p8  = (const float*)d_in[2];
    // d_in[3] = p4 (unused by the reference forward)
    const float* b32 = (const float*)d_in[4];
    const float* b16 = (const float*)d_in[5];
    const float* b8  = (const float*)d_in[6];
    const float* s32 = (const float*)d_in[7];
    const float* s16 = (const float*)d_in[8];
    const float* s8  = (const float*)d_in[9];
    float* out = (float*)d_out;

    // side streams + fork/join events: created ONCE on the first (uncaptured)
    // correctness call; later captured calls record a 3-branch DAG.
    static cudaStream_t st1 = nullptr, st2 = nullptr;
    static cudaEvent_t  ev0, ev1, ev2;
    if (st1 == nullptr) {
        cudaStreamCreateWithFlags(&st1, cudaStreamNonBlocking);
        cudaStreamCreateWithFlags(&st2, cudaStreamNonBlocking);
        cudaEventCreateWithFlags(&ev0, cudaEventDisableTiming);
        cudaEventCreateWithFlags(&ev1, cudaEventDisableTiming);
        cudaEventCreateWithFlags(&ev2, cudaEventDisableTiming);
        // keys (48KB) + boxes (96KB) = 144KB dynamic smem
        cudaFuncSetAttribute(nms_kernel,
                             cudaFuncAttributeMaxDynamicSharedMemorySize,
                             (int)((size_t)NBOX * (8 + 16)));
    }
    const size_t NMS_SMEM = (size_t)NBOX * (8 + 16);

    // fork
    cudaEventRecord(ev0, 0);
    cudaStreamWaitEvent(st1, ev0, 0);
    cudaStreamWaitEvent(st2, ev0, 0);

    // branch 0 (default stream): level 3 — the long pole, launched first
    nms_kernel<<<2, NMS_BD, NMS_SMEM, 0>>>(b32, b16, b8, s32, s16, s8, 3);
    // branch 1: level 1
    nms_kernel<<<2, NMS_BD, NMS_SMEM, st1>>>(b32, b16, b8, s32, s16, s8, 1);
    // branch 2: level 2
    nms_kernel<<<2, NMS_BD, NMS_SMEM, st2>>>(b32, b16, b8, s32, s16, s8, 2);

    dim3 rg(BATCH * 64, CCH / CPB);
    roi_kernel<<<rg, 224, 0, st1>>>(p32, b32, b16, b8, out, 0, 28);
    roi_kernel<<<rg, 224, 0, st2>>>(p16, b32, b16, b8, out, 1, 56);
    roi_kernel<<<rg, 224, 0, 0  >>>(p8,  b32, b16, b8, out, 2, 112);

    // join
    cudaEventRecord(ev1, st1);
    cudaEventRecord(ev2, st2);
    cudaStreamWaitEvent(0, ev1, 0);
    cudaStreamWaitEvent(0, ev2, 0);
}

// round 13
// speedup vs baseline: 1.5744x; 1.0238x over previous
#include <cuda_runtime.h>
#include <cstdint>
#include <cstddef>

// ----------------------------------------------------------------------------
// InstanceSegmentationHead, iteration-level pipelined:
// one nms kernel (6 blocks, high-priority stream) streams selections into
// g_sel via volatile stores; one roi kernel (default stream, all levels)
// spin-waits per-block on its single selection and runs concurrently.
// B=2, C=256, N=2048 per source, feature sizes 28/56/112.
// ----------------------------------------------------------------------------

#define NBOX 6144
#define BATCH 2
#define CCH 256
#define KKEEP 64
#define OUTP 14
#define CPB 16              // channels per roi block

// ---------------- scratch (__device__ globals; no allocation) ---------------
// -2 = not ready (set by init_kernel); -1 = no selection; >=0 = box index
__device__ int g_sel[6][KKEEP];

// order-preserving float->uint mapping (monotonic)
__device__ __forceinline__ unsigned ford(float f) {
    unsigned u = __float_as_uint(f);
    return (u & 0x80000000u) ? ~u : (u | 0x80000000u);
}

// ------------------------- stage 0: sentinel init ----------------------------
__global__ void init_kernel() {
    ((volatile int*)g_sel)[threadIdx.x] = -2;    // 384 = 6*64 threads
}

// --------------------- fused prep + greedy NMS (all levels) ------------------
// 6 blocks: bl = blockIdx.x -> (b = bl/3, level = bl%3+1). Block scans all 6144
// raw boxes, compacts its level into SMEM (key u64 + xyxy float4), then runs
// register-resident NMS, publishing each selection immediately (volatile).
#define NMS_BD 512
#define NMS_U  12        // 512*12 = 6144 = NBOX

__global__ void __launch_bounds__(NMS_BD, 1) nms_kernel(
    const float* __restrict__ b32, const float* __restrict__ b16,
    const float* __restrict__ b8,
    const float* __restrict__ s32, const float* __restrict__ s16,
    const float* __restrict__ s8) {
    extern __shared__ char smraw[];
    unsigned long long* skey = (unsigned long long*)smraw;           // 48KB
    float4* sbox = (float4*)(smraw + (size_t)NBOX * 8);              // 96KB

    __shared__ unsigned long long rk[16];
    __shared__ unsigned long long s_wk;
    __shared__ int                s_n;

    int bl   = blockIdx.x;           // 0..5
    int b    = bl / 3;
    int ltgt = bl - b * 3 + 1;       // target level 1..3
    int tid  = threadIdx.x;
    int lane = tid & 31;

    if (tid == 0) s_n = 0;
    __syncthreads();

    // ---- fused prep: scan all boxes, keep this level's ----
    for (int j = tid; j < NBOX; j += NMS_BD) {
        int src = j >> 11;           // 0,1,2
        int jj  = j & 2047;
        const float* bp; const float* sp; float s;
        if (src == 0)      { bp = b32; sp = s32; s = 32.f; }
        else if (src == 1) { bp = b16; sp = s16; s = 16.f; }
        else               { bp = b8;  sp = s8;  s = 8.f;  }
        const float4 bx = *(const float4*)(bp + ((size_t)(b * 2048 + jj)) * 4);
        float sc = sp[(size_t)b * 2048 + jj];

        // level from UNscaled size: clip(floor(3 + log2(sqrt(w*h)/224)), 1, 4)
        float sz = sqrtf(__fmul_rn(bx.z, bx.w));
        float lv = floorf(__fadd_rn(3.0f, log2f(__fdiv_rn(sz, 224.0f))));
        lv = fminf(fmaxf(lv, 1.0f), 4.0f);

        if ((int)lv == ltgt) {
            // scaled xyxy (single-op IEEE rounding, no fma contraction)
            float scx = __fmul_rn(bx.x, s), scy = __fmul_rn(bx.y, s);
            float sw  = __fmul_rn(bx.z, s), sh  = __fmul_rn(bx.w, s);
            float hx  = __fmul_rn(sw, 0.5f), hy = __fmul_rn(sh, 0.5f);
            float x1  = __fsub_rn(scx, hx), y1 = __fsub_rn(scy, hy);
            float x2  = __fadd_rn(scx, hx), y2 = __fadd_rn(scy, hy);
            int pos = atomicAdd(&s_n, 1);
            // higher score wins; ties -> smaller orig index; low bits = slot
            skey[pos] = ((unsigned long long)ford(sc) << 26) |
                        ((unsigned long long)(8191 - j) << 13) |
                        (unsigned long long)pos;
            sbox[pos] = make_float4(x1, y1, x2, y2);
        }
    }
    __syncthreads();
    int n = s_n;

    // ---- register-resident load ----
    unsigned long long key[NMS_U];
    float4             box[NMS_U];
    float              area[NMS_U];
    #pragma unroll
    for (int u = 0; u < NMS_U; ++u) {
        int j = tid + u * NMS_BD;
        key[u]  = 0ull;
        box[u]  = make_float4(0.f, 0.f, 0.f, 0.f);
        area[u] = 0.f;
        if (j < n) {
            key[u] = skey[j];
            float4 bb = sbox[j];
            box[u]  = bb;
            area[u] = __fmul_rn(fmaxf(__fsub_rn(bb.z, bb.x), 0.f),
                                fmaxf(__fsub_rn(bb.w, bb.y), 0.f));
        }
    }
    __syncthreads();

    const float MLO = 2.9802322387695312e-8f;    // 2^-25 = half-ulp of 0.7f

    // initial "winner" suppresses nothing (intersection clamps to 0)
    float4 wb = make_float4(1e30f, 1e30f, 1e30f, 1e30f);

    int it = 0;
    for (; it < KKEEP; ++it) {
        float a = __fmul_rn(fmaxf(__fsub_rn(wb.z, wb.x), 0.f),
                            fmaxf(__fsub_rn(wb.w, wb.y), 0.f));

        unsigned long long bk = 0ull;

        #pragma unroll
        for (int u = 0; u < NMS_U; ++u) {
            if (u * NMS_BD >= n) break;          // uniform: skip unused tail
            float4 bb = box[u];
            float ix1 = fmaxf(wb.x, bb.x), iy1 = fmaxf(wb.y, bb.y);
            float ix2 = fminf(wb.z, bb.z), iy2 = fminf(wb.w, bb.w);
            float inter = __fmul_rn(fmaxf(__fsub_rn(ix2, ix1), 0.f),
                                    fmaxf(__fsub_rn(iy2, iy1), 0.f));
            float denom = __fadd_rn(__fsub_rn(__fadd_rn(a, area[u]), inter), 1e-9f);
            // suppress <=> rn(inter/denom) > 0.7f <=> inter >= (0.7f+2^-25)*denom
            float dd = __fmaf_rn(-0.7f, denom, inter);
            float tt = __fmul_rn(MLO, denom);    // exact (power of two)
            if (dd >= tt) key[u] = 0ull;         // dead keys can never win
            if (key[u] > bk) bk = key[u];
        }

        // block argmax of key (u64 only)
        #pragma unroll
        for (int off = 16; off; off >>= 1) {
            unsigned long long ok = __shfl_down_sync(0xFFFFFFFFu, bk, off);
            if (ok > bk) bk = ok;
        }
        if (lane == 0) rk[tid >> 5] = bk;
        __syncthreads();
        if (tid < 32) {
            bk = (lane < 16) ? rk[lane] : 0ull;
            #pragma unroll
            for (int off = 8; off; off >>= 1) {
                unsigned long long ok = __shfl_down_sync(0xFFFFFFFFu, bk, off);
                if (ok > bk) bk = ok;
            }
            if (tid == 0) s_wk = bk;
        }
        __syncthreads();

        unsigned long long wk = s_wk;
        if (wk == 0ull) break;                   // all suppressed -> rest are -1
        wb = sbox[(int)(wk & 8191u)];            // broadcast LDS
        if (tid == 0)                            // publish immediately (volatile)
            ((volatile int*)g_sel)[bl * KKEEP + it] =
                8191 - (int)((wk >> 13) & 8191u);
    }

    for (int j = it + tid; j < KKEEP; j += NMS_BD)
        ((volatile int*)g_sel)[bl * KKEEP + j] = -1;
}

// ------------------------- ROI align (all levels, fused) ---------------------
// grid.x = B*192 (b = x/192, k = x%192), grid.y = 16 channel groups of CPB=16.
// 224 threads. Spin-waits for its selection, then one of 4 paths:
// corner-clamped / x-clamped / y-clamped / full bilinear.
__global__ void __launch_bounds__(224, 4) roi_kernel(
    const float* __restrict__ p32, const float* __restrict__ p16,
    const float* __restrict__ p8,
    const float* __restrict__ b32, const float* __restrict__ b16,
    const float* __restrict__ b8,
    float* __restrict__ out) {
    __shared__ int s_sel;
    int bk  = blockIdx.x;          // 0..383
    int b   = bk / 192;
    int k   = bk - b * 192;
    int lvl = k >> 6;              // 0,1,2
    int kk  = k & 63;
    int cg  = blockIdx.y * CPB;
    int tid = threadIdx.x;

    // spin for our selection (written exactly once per replay; -2 = not ready)
    if (tid == 0) {
        volatile int* vp = ((volatile int*)g_sel) + (b * 3 + lvl) * KKEEP + kk;
        int v = *vp;
        while (v == -2) { __nanosleep(200); v = *vp; }
        s_sel = v;
    }
    __syncthreads();
    int sel = s_sel;

    float* o = out + (size_t)bk * (CCH * OUTP * OUTP) + (size_t)cg * (OUTP * OUTP);
    float4* o4 = (float4*)o;       // 784B-aligned

    if (sel < 0) {
        float4 z = make_float4(0.f, 0.f, 0.f, 0.f);
        for (int i = tid; i < CPB * 49; i += 224) o4[i] = z;
        return;
    }

    int S = (lvl == 0) ? 28 : (lvl == 1) ? 56 : 112;
    int SS = S * S;
    const float* fbase = ((lvl == 0) ? p32 : (lvl == 1) ? p16 : p8)
                         + ((size_t)b * CCH + cg) * (size_t)SS;

    // recompute the scaled cxcywh box from raw inputs (bit-exact vs the
    // reference's scaled concat); fed into roi_align as x1,y1,x2,y2.
    int src = sel >> 11;
    int jj  = sel & 2047;
    const float* bpp = ((src == 0) ? b32 : (src == 1) ? b16 : b8)
                       + ((size_t)(b * 2048 + jj)) * 4;
    float s = (src == 0) ? 32.f : (src == 1) ? 16.f : 8.f;
    float x1 = __fmul_rn(bpp[0], s);
    float y1 = __fmul_rn(bpp[1], s);
    float x2 = __fmul_rn(bpp[2], s);
    float y2 = __fmul_rn(bpp[3], s);
    float bw = __fdiv_rn(__fsub_rn(x2, x1), 14.0f);
    float bh = __fdiv_rn(__fsub_rn(y2, y1), 14.0f);

    float lim = (float)(S - 1);
    bool xc = (x1 >= lim) && (bw >= 0.f);   // all x-samples clamp to S-1, fx=0
    bool yc = (y1 >= lim) && (bh >= 0.f);   // all y-samples clamp to S-1, fy=0

    // ---- corner path: tile == F[c][S*S-1] exactly ----
    if (xc && yc) {
        int c = tid / 14;                 // 224 = 16*14: c in [0,16), r in [0,14)
        int r = tid - c * 14;
        float v = __ldg(fbase + (size_t)c * SS + (SS - 1));
        float4 v4 = make_float4(v, v, v, v);
        int base = c * 49;
        #pragma unroll
        for (int i = r; i < 49; i += 14) o4[base + i] = v4;
        return;
    }

    // ---- x-clamped: every row constant; v depends on (c, oy) only ----
    if (xc) {
        int c  = tid / 14;
        int oy = tid - c * 14;
        const float* f = fbase + (size_t)c * SS;
        float acc = 0.f;
        #pragma unroll
        for (int q = 0; q < 2; ++q) {
            float ty = __fadd_rn((float)oy, q ? 0.75f : 0.25f);
            float cy = __fadd_rn(y1, __fmul_rn(ty, bh));
            cy = fminf(fmaxf(cy, 0.0f), lim);
            float c0 = floorf(cy);
            float fy = __fsub_rn(cy, c0);
            int iy0 = (int)c0;
            int iy1 = min(iy0 + 1, S - 1);
            float g0 = __ldg(f + iy0 * S + (S - 1));
            float g1 = __ldg(f + iy1 * S + (S - 1));
            acc += g0 * (1.0f - fy) + g1 * fy;
        }
        float v = acc * 0.5f;             // mean of 4 samples, pairs equal
        float* op = o + c * 196 + oy * 14;
        #pragma unroll
        for (int i = 0; i < 14; ++i) op[i] = v;
        return;
    }

    // ---- y-clamped: every column constant; v depends on (c, ox) only ----
    if (yc) {
        int c  = tid / 14;
        int ox = tid - c * 14;
        const float* f = fbase + (size_t)c * SS + (size_t)(S - 1) * S;  // last row
        float acc = 0.f;
        #pragma unroll
        for (int q = 0; q < 2; ++q) {
            float tx = __fadd_rn((float)ox, q ? 0.75f : 0.25f);
            float cx = __fadd_rn(x1, __fmul_rn(tx, bw));
            cx = fminf(fmaxf(cx, 0.0f), lim);
            float d0 = floorf(cx);
            float fx = __fsub_rn(cx, d0);
            int ix0 = (int)d0;
            int ix1 = min(ix0 + 1, S - 1);
            float g0 = __ldg(f + ix0);
            float g1 = __ldg(f + ix1);
            acc += g0 * (1.0f - fx) + g1 * fx;
        }
        float v = acc * 0.5f;
        float* op = o + c * 196 + ox;
        #pragma unroll
        for (int i = 0; i < 14; ++i) op[i * 14] = v;
        return;
    }

    // ---- full bilinear path ----
    if (tid >= OUTP * OUTP) return;             // 196 active threads

    int p  = tid;
    int oy = p / OUTP;
    int ox = p - oy * OUTP;

    int   iy0[2], iy1[2], ix0[2], ix1[2];
    float fy[2], fx[2];
    #pragma unroll
    for (int q = 0; q < 2; ++q) {
        float ty = __fadd_rn((float)oy, q ? 0.75f : 0.25f);
        float cy = __fadd_rn(y1, __fmul_rn(ty, bh));
        cy = fminf(fmaxf(cy, 0.0f), lim);
        float c0 = floorf(cy);
        fy[q]  = __fsub_rn(cy, c0);
        iy0[q] = (int)c0;
        iy1[q] = min(iy0[q] + 1, S - 1);

        float tx = __fadd_rn((float)ox, q ? 0.75f : 0.25f);
        float cx = __fadd_rn(x1, __fmul_rn(tx, bw));
        cx = fminf(fmaxf(cx, 0.0f), lim);
        float d0 = floorf(cx);
        fx[q]  = __fsub_rn(cx, d0);
        ix0[q] = (int)d0;
        ix1[q] = min(ix0[q] + 1, S - 1);
    }

    // 16 corner offsets + weights (0.25 mean folded in)
    int   off[16];
    float w[16];
    #pragma unroll
    for (int sy = 0; sy < 2; ++sy) {
        #pragma unroll
        for (int sx = 0; sx < 2; ++sx) {
            int s4 = (sy * 2 + sx) * 4;
            int Y0 = iy0[sy] * S, Y1 = iy1[sy] * S;
            float gy = fy[sy], igy = 1.0f - gy;
            float gx = fx[sx], igx = 1.0f - gx;
            off[s4 + 0] = Y0 + ix0[sx];  w[s4 + 0] = igy * igx * 0.25f;
            off[s4 + 1] = Y0 + ix1[sx];  w[s4 + 1] = igy * gx  * 0.25f;
            off[s4 + 2] = Y1 + ix0[sx];  w[s4 + 2] = gy  * igx * 0.25f;
            off[s4 + 3] = Y1 + ix1[sx];  w[s4 + 3] = gy  * gx  * 0.25f;
        }
    }

    const float* f  = fbase;
    float*       op = o + p;
    #pragma unroll 2
    for (int c = 0; c < CPB; ++c) {
        float a0 = 0.f, a1 = 0.f, a2 = 0.f, a3 = 0.f;
        #pragma unroll
        for (int i = 0; i < 4; ++i) {
            a0 = fmaf(__ldg(f + off[4 * i + 0]), w[4 * i + 0], a0);
            a1 = fmaf(__ldg(f + off[4 * i + 1]), w[4 * i + 1], a1);
            a2 = fmaf(__ldg(f + off[4 * i + 2]), w[4 * i + 2], a2);
            a3 = fmaf(__ldg(f + off[4 * i + 3]), w[4 * i + 3], a3);
        }
        *op = (a0 + a1) + (a2 + a3);
        f  += SS;
        op += OUTP * OUTP;
    }
}

// ------------------------------- launcher ------------------------------------
extern "C" void kernel_launch(void* const* d_in, const int* in_sizes, int n_in,
                              void* d_out, int out_size) {
    const float* p32 = (const float*)d_in[0];
    const float* p16 = (const float*)d_in[1];
    const float* p8  = (const float*)d_in[2];
    // d_in[3] = p4 (unused by the reference forward)
    const float* b32 = (const float*)d_in[4];
    const float* b16 = (const float*)d_in[5];
    const float* b8  = (const float*)d_in[6];
    const float* s32 = (const float*)d_in[7];
    const float* s16 = (const float*)d_in[8];
    const float* s8  = (const float*)d_in[9];
    float* out = (float*)d_out;

    // ONE extra stream + TWO events (below R11's proven-passing footprint).
    // Created once on the first (uncaptured) correctness call.
    static cudaStream_t sn = nullptr;      // high-priority: nms
    static cudaEvent_t  ev0, ev1;
    if (sn == nullptr) {
        int loPri, hiPri;
        cudaDeviceGetStreamPriorityRange(&loPri, &hiPri);
        cudaStreamCreateWithPriority(&sn, cudaStreamNonBlocking, hiPri);
        cudaEventCreateWithFlags(&ev0, cudaEventDisableTiming);
        cudaEventCreateWithFlags(&ev1, cudaEventDisableTiming);
        // keys (48KB) + boxes (96KB) = 144KB dynamic smem
        cudaFuncSetAttribute(nms_kernel,
                             cudaFuncAttributeMaxDynamicSharedMemorySize,
                             (int)((size_t)NBOX * (8 + 16)));
    }
    const size_t NMS_SMEM = (size_t)NBOX * (8 + 16);

    // sentinel init on default stream, then fork to the nms stream
    init_kernel<<<1, 6 * KKEEP>>>();
    cudaEventRecord(ev0, 0);
    cudaStreamWaitEvent(sn, ev0, 0);

    // nms FIRST on the high-priority stream (6 blocks -> placed immediately)
    nms_kernel<<<6, NMS_BD, NMS_SMEM, sn>>>(b32, b16, b8, s32, s16, s8);

    // roi on the default stream; blocks spin on their own selection
    dim3 rg(BATCH * 192, CCH / CPB);
    roi_kernel<<<rg, 224>>>(p32, p16, p8, b32, b16, b8, out);

    // join the nms stream back into the default stream
    cudaEventRecord(ev1, sn);
    cudaStreamWaitEvent(0, ev1, 0);
}

// round 14
// speedup vs baseline: 1.9513x; 1.2394x over previous
#include <cuda_runtime.h>
#include <cstdint>
#include <cstddef>

// ----------------------------------------------------------------------------
// InstanceSegmentationHead, iteration-level pipelined:
//   init -> [hi-pri] nms (6 blocks, signals residency, streams selections)
//        -> [default] gate (waits nms resident) -> roi (kk-major order,
//           96KB smem fence keeps roi off the 6 nms SMs, spin-waits per tile).
// B=2, C=256, N=2048 per source, feature sizes 28/56/112.
// ----------------------------------------------------------------------------

#define NBOX 6144
#define BATCH 2
#define CCH 256
#define KKEEP 64
#define OUTP 14
#define CPB 16              // channels per roi block
#define ROI_SMEM (96 * 1024)   // fence: nms SM has 228-144=84KB free < 96KB

// ---------------- scratch (__device__ globals; no allocation) ---------------
// -2 = not ready (set by init_kernel); -1 = no selection; >=0 = box index
__device__ int g_sel[6][KKEEP];
__device__ int g_ready;     // # of resident nms blocks (reset by init)

// order-preserving float->uint mapping (monotonic)
__device__ __forceinline__ unsigned ford(float f) {
    unsigned u = __float_as_uint(f);
    return (u & 0x80000000u) ? ~u : (u | 0x80000000u);
}

// ------------------------- stage 0: sentinel init ----------------------------
__global__ void init_kernel() {
    int t = threadIdx.x;
    if (t < 6 * KKEEP) ((volatile int*)g_sel)[t] = -2;
    if (t == 6 * KKEEP) *(volatile int*)&g_ready = 0;
}

// ----------------- gate: wait until all 6 nms blocks are resident ------------
__global__ void gate_kernel() {
    if (threadIdx.x == 0) {
        volatile int* vr = &g_ready;
        while (*vr < 6) __nanosleep(200);
    }
}

// --------------------- fused prep + greedy NMS (all levels) ------------------
// 6 blocks: bl = blockIdx.x -> (b = bl/3, level = bl%3+1). Block scans all 6144
// raw boxes, compacts its level into SMEM (key u64 + xyxy float4), then runs
// register-resident NMS, publishing each selection immediately (volatile).
#define NMS_BD 512
#define NMS_U  12        // 512*12 = 6144 = NBOX

__global__ void __launch_bounds__(NMS_BD, 1) nms_kernel(
    const float* __restrict__ b32, const float* __restrict__ b16,
    const float* __restrict__ b8,
    const float* __restrict__ s32, const float* __restrict__ s16,
    const float* __restrict__ s8) {
    extern __shared__ char smraw[];
    unsigned long long* skey = (unsigned long long*)smraw;           // 48KB
    float4* sbox = (float4*)(smraw + (size_t)NBOX * 8);              // 96KB

    __shared__ unsigned long long rk[16];
    __shared__ unsigned long long s_wk;
    __shared__ int                s_n;

    int bl   = blockIdx.x;           // 0..5
    int b    = bl / 3;
    int ltgt = bl - b * 3 + 1;       // target level 1..3
    int tid  = threadIdx.x;
    int lane = tid & 31;

    if (tid == 0) { atomicAdd(&g_ready, 1); s_n = 0; }   // signal residency
    __syncthreads();

    // ---- fused prep: scan all boxes, keep this level's ----
    for (int j = tid; j < NBOX; j += NMS_BD) {
        int src = j >> 11;           // 0,1,2
        int jj  = j & 2047;
        const float* bp; const float* sp; float s;
        if (src == 0)      { bp = b32; sp = s32; s = 32.f; }
        else if (src == 1) { bp = b16; sp = s16; s = 16.f; }
        else               { bp = b8;  sp = s8;  s = 8.f;  }
        const float4 bx = *(const float4*)(bp + ((size_t)(b * 2048 + jj)) * 4);
        float sc = sp[(size_t)b * 2048 + jj];

        // level from UNscaled size: clip(floor(3 + log2(sqrt(w*h)/224)), 1, 4)
        float sz = sqrtf(__fmul_rn(bx.z, bx.w));
        float lv = floorf(__fadd_rn(3.0f, log2f(__fdiv_rn(sz, 224.0f))));
        lv = fminf(fmaxf(lv, 1.0f), 4.0f);

        if ((int)lv == ltgt) {
            // scaled xyxy (single-op IEEE rounding, no fma contraction)
            float scx = __fmul_rn(bx.x, s), scy = __fmul_rn(bx.y, s);
            float sw  = __fmul_rn(bx.z, s), sh  = __fmul_rn(bx.w, s);
            float hx  = __fmul_rn(sw, 0.5f), hy = __fmul_rn(sh, 0.5f);
            float x1  = __fsub_rn(scx, hx), y1 = __fsub_rn(scy, hy);
            float x2  = __fadd_rn(scx, hx), y2 = __fadd_rn(scy, hy);
            int pos = atomicAdd(&s_n, 1);
            // higher score wins; ties -> smaller orig index; low bits = slot
            skey[pos] = ((unsigned long long)ford(sc) << 26) |
                        ((unsigned long long)(8191 - j) << 13) |
                        (unsigned long long)pos;
            sbox[pos] = make_float4(x1, y1, x2, y2);
        }
    }
    __syncthreads();
    int n = s_n;

    // ---- register-resident load ----
    unsigned long long key[NMS_U];
    float4             box[NMS_U];
    float              area[NMS_U];
    #pragma unroll
    for (int u = 0; u < NMS_U; ++u) {
        int j = tid + u * NMS_BD;
        key[u]  = 0ull;
        box[u]  = make_float4(0.f, 0.f, 0.f, 0.f);
        area[u] = 0.f;
        if (j < n) {
            key[u] = skey[j];
            float4 bb = sbox[j];
            box[u]  = bb;
            area[u] = __fmul_rn(fmaxf(__fsub_rn(bb.z, bb.x), 0.f),
                                fmaxf(__fsub_rn(bb.w, bb.y), 0.f));
        }
    }
    __syncthreads();

    const float MLO = 2.9802322387695312e-8f;    // 2^-25 = half-ulp of 0.7f

    // initial "winner" suppresses nothing (intersection clamps to 0)
    float4 wb = make_float4(1e30f, 1e30f, 1e30f, 1e30f);

    int it = 0;
    for (; it < KKEEP; ++it) {
        float a = __fmul_rn(fmaxf(__fsub_rn(wb.z, wb.x), 0.f),
                            fmaxf(__fsub_rn(wb.w, wb.y), 0.f));

        unsigned long long bk = 0ull;

        #pragma unroll
        for (int u = 0; u < NMS_U; ++u) {
            if (u * NMS_BD >= n) break;          // uniform: skip unused tail
            float4 bb = box[u];
            float ix1 = fmaxf(wb.x, bb.x), iy1 = fmaxf(wb.y, bb.y);
            float ix2 = fminf(wb.z, bb.z), iy2 = fminf(wb.w, bb.w);
            float inter = __fmul_rn(fmaxf(__fsub_rn(ix2, ix1), 0.f),
                                    fmaxf(__fsub_rn(iy2, iy1), 0.f));
            float denom = __fadd_rn(__fsub_rn(__fadd_rn(a, area[u]), inter), 1e-9f);
            // suppress <=> rn(inter/denom) > 0.7f <=> inter >= (0.7f+2^-25)*denom
            float dd = __fmaf_rn(-0.7f, denom, inter);
            float tt = __fmul_rn(MLO, denom);    // exact (power of two)
            if (dd >= tt) key[u] = 0ull;         // dead keys can never win
            if (key[u] > bk) bk = key[u];
        }

        // block argmax of key (u64 only)
        #pragma unroll
        for (int off = 16; off; off >>= 1) {
            unsigned long long ok = __shfl_down_sync(0xFFFFFFFFu, bk, off);
            if (ok > bk) bk = ok;
        }
        if (lane == 0) rk[tid >> 5] = bk;
        __syncthreads();
        if (tid < 32) {
            bk = (lane < 16) ? rk[lane] : 0ull;
            #pragma unroll
            for (int off = 8; off; off >>= 1) {
                unsigned long long ok = __shfl_down_sync(0xFFFFFFFFu, bk, off);
                if (ok > bk) bk = ok;
            }
            if (tid == 0) s_wk = bk;
        }
        __syncthreads();

        unsigned long long wk = s_wk;
        if (wk == 0ull) break;                   // all suppressed -> rest are -1
        wb = sbox[(int)(wk & 8191u)];            // broadcast LDS
        if (tid == 0)                            // publish immediately (volatile)
            ((volatile int*)g_sel)[bl * KKEEP + it] =
                8191 - (int)((wk >> 13) & 8191u);
    }

    for (int j = it + tid; j < KKEEP; j += NMS_BD)
        ((volatile int*)g_sel)[bl * KKEEP + j] = -1;
}

// ------------------------- ROI align (all levels, fused) ---------------------
// 1-D grid of 6144 blocks in kk-MAJOR order: early-dispatched blocks need the
// earliest NMS iterations -> spinners release at the production rate.
// idx -> kk = idx/96; u = (idx%96)/16 -> (b,lvl); cg = (idx%16)*16.
// 96KB dynamic smem (unused) fences roi off the 6 nms SMs.
__global__ void __launch_bounds__(224, 4) roi_kernel(
    const float* __restrict__ p32, const float* __restrict__ p16,
    const float* __restrict__ p8,
    const float* __restrict__ b32, const float* __restrict__ b16,
    const float* __restrict__ b8,
    float* __restrict__ out) {
    extern __shared__ char fence_smem[];   // intentionally unused (SM fence)
    (void)fence_smem;
    __shared__ int s_sel;

    int idx = blockIdx.x;          // 0..6143
    int kk  = idx / 96;
    int r   = idx - kk * 96;
    int u   = r >> 4;              // 0..5 = b*3+lvl
    int b   = (u >= 3) ? 1 : 0;
    int lvl = u - b * 3;
    int k   = lvl * 64 + kk;
    int bk  = b * 192 + k;
    int cg  = (r & 15) * CPB;
    int tid = threadIdx.x;

    // spin for our selection (written exactly once per replay; -2 = not ready)
    if (tid == 0) {
        volatile int* vp = ((volatile int*)g_sel) + (b * 3 + lvl) * KKEEP + kk;
        int v = *vp;
        while (v == -2) { __nanosleep(200); v = *vp; }
        s_sel = v;
    }
    __syncthreads();
    int sel = s_sel;

    float* o = out + (size_t)bk * (CCH * OUTP * OUTP) + (size_t)cg * (OUTP * OUTP);
    float4* o4 = (float4*)o;       // 784B-aligned

    if (sel < 0) {
        float4 z = make_float4(0.f, 0.f, 0.f, 0.f);
        for (int i = tid; i < CPB * 49; i += 224) o4[i] = z;
        return;
    }

    int S = (lvl == 0) ? 28 : (lvl == 1) ? 56 : 112;
    int SS = S * S;
    const float* fbase = ((lvl == 0) ? p32 : (lvl == 1) ? p16 : p8)
                         + ((size_t)b * CCH + cg) * (size_t)SS;

    // recompute the scaled cxcywh box from raw inputs (bit-exact vs the
    // reference's scaled concat); fed into roi_align as x1,y1,x2,y2.
    int src = sel >> 11;
    int jj  = sel & 2047;
    const float* bpp = ((src == 0) ? b32 : (src == 1) ? b16 : b8)
                       + ((size_t)(b * 2048 + jj)) * 4;
    float s = (src == 0) ? 32.f : (src == 1) ? 16.f : 8.f;
    float x1 = __fmul_rn(bpp[0], s);
    float y1 = __fmul_rn(bpp[1], s);
    float x2 = __fmul_rn(bpp[2], s);
    float y2 = __fmul_rn(bpp[3], s);
    float bw = __fdiv_rn(__fsub_rn(x2, x1), 14.0f);
    float bh = __fdiv_rn(__fsub_rn(y2, y1), 14.0f);

    float lim = (float)(S - 1);
    bool xc = (x1 >= lim) && (bw >= 0.f);   // all x-samples clamp to S-1, fx=0
    bool yc = (y1 >= lim) && (bh >= 0.f);   // all y-samples clamp to S-1, fy=0

    // ---- corner path: tile == F[c][S*S-1] exactly ----
    if (xc && yc) {
        int c = tid / 14;                 // 224 = 16*14: c in [0,16), r in [0,14)
        int rr = tid - c * 14;
        float v = __ldg(fbase + (size_t)c * SS + (SS - 1));
        float4 v4 = make_float4(v, v, v, v);
        int base = c * 49;
        #pragma unroll
        for (int i = rr; i < 49; i += 14) o4[base + i] = v4;
        return;
    }

    // ---- x-clamped: every row constant; v depends on (c, oy) only ----
    if (xc) {
        int c  = tid / 14;
        int oy = tid - c * 14;
        const float* f = fbase + (size_t)c * SS;
        float acc = 0.f;
        #pragma unroll
        for (int q = 0; q < 2; ++q) {
            float ty = __fadd_rn((float)oy, q ? 0.75f : 0.25f);
            float cy = __fadd_rn(y1, __fmul_rn(ty, bh));
            cy = fminf(fmaxf(cy, 0.0f), lim);
            float c0 = floorf(cy);
            float fy = __fsub_rn(cy, c0);
            int iy0 = (int)c0;
            int iy1 = min(iy0 + 1, S - 1);
            float g0 = __ldg(f + iy0 * S + (S - 1));
            float g1 = __ldg(f + iy1 * S + (S - 1));
            acc += g0 * (1.0f - fy) + g1 * fy;
        }
        float v = acc * 0.5f;             // mean of 4 samples, pairs equal
        float* op = o + c * 196 + oy * 14;
        #pragma unroll
        for (int i = 0; i < 14; ++i) op[i] = v;
        return;
    }

    // ---- y-clamped: every column constant; v depends on (c, ox) only ----
    if (yc) {
        int c  = tid / 14;
        int ox = tid - c * 14;
        const float* f = fbase + (size_t)c * SS + (size_t)(S - 1) * S;  // last row
        float acc = 0.f;
        #pragma unroll
        for (int q = 0; q < 2; ++q) {
            float tx = __fadd_rn((float)ox, q ? 0.75f : 0.25f);
            float cx = __fadd_rn(x1, __fmul_rn(tx, bw));
            cx = fminf(fmaxf(cx, 0.0f), lim);
            float d0 = floorf(cx);
            float fx = __fsub_rn(cx, d0);
            int ix0 = (int)d0;
            int ix1 = min(ix0 + 1, S - 1);
            float g0 = __ldg(f + ix0);
            float g1 = __ldg(f + ix1);
            acc += g0 * (1.0f - fx) + g1 * fx;
        }
        float v = acc * 0.5f;
        float* op = o + c * 196 + ox;
        #pragma unroll
        for (int i = 0; i < 14; ++i) op[i * 14] = v;
        return;
    }

    // ---- full bilinear path ----
    if (tid >= OUTP * OUTP) return;             // 196 active threads

    int p  = tid;
    int oy = p / OUTP;
    int ox = p - oy * OUTP;

    int   iy0[2], iy1[2], ix0[2], ix1[2];
    float fy[2], fx[2];
    #pragma unroll
    for (int q = 0; q < 2; ++q) {
        float ty = __fadd_rn((float)oy, q ? 0.75f : 0.25f);
        float cy = __fadd_rn(y1, __fmul_rn(ty, bh));
        cy = fminf(fmaxf(cy, 0.0f), lim);
        float c0 = floorf(cy);
        fy[q]  = __fsub_rn(cy, c0);
        iy0[q] = (int)c0;
        iy1[q] = min(iy0[q] + 1, S - 1);

        float tx = __fadd_rn((float)ox, q ? 0.75f : 0.25f);
        float cx = __fadd_rn(x1, __fmul_rn(tx, bw));
        cx = fminf(fmaxf(cx, 0.0f), lim);
        float d0 = floorf(cx);
        fx[q]  = __fsub_rn(cx, d0);
        ix0[q] = (int)d0;
        ix1[q] = min(ix0[q] + 1, S - 1);
    }

    // 16 corner offsets + weights (0.25 mean folded in)
    int   off[16];
    float w[16];
    #pragma unroll
    for (int sy = 0; sy < 2; ++sy) {
        #pragma unroll
        for (int sx = 0; sx < 2; ++sx) {
            int s4 = (sy * 2 + sx) * 4;
            int Y0 = iy0[sy] * S, Y1 = iy1[sy] * S;
            float gy = fy[sy], igy = 1.0f - gy;
            float gx = fx[sx], igx = 1.0f - gx;
            off[s4 + 0] = Y0 + ix0[sx];  w[s4 + 0] = igy * igx * 0.25f;
            off[s4 + 1] = Y0 + ix1[sx];  w[s4 + 1] = igy * gx  * 0.25f;
            off[s4 + 2] = Y1 + ix0[sx];  w[s4 + 2] = gy  * igx * 0.25f;
            off[s4 + 3] = Y1 + ix1[sx];  w[s4 + 3] = gy  * gx  * 0.25f;
        }
    }

    const float* f  = fbase;
    float*       op = o + p;
    #pragma unroll 2
    for (int c = 0; c < CPB; ++c) {
        float a0 = 0.f, a1 = 0.f, a2 = 0.f, a3 = 0.f;
        #pragma unroll
        for (int i = 0; i < 4; ++i) {
            a0 = fmaf(__ldg(f + off[4 * i + 0]), w[4 * i + 0], a0);
            a1 = fmaf(__ldg(f + off[4 * i + 1]), w[4 * i + 1], a1);
            a2 = fmaf(__ldg(f + off[4 * i + 2]), w[4 * i + 2], a2);
            a3 = fmaf(__ldg(f + off[4 * i + 3]), w[4 * i + 3], a3);
        }
        *op = (a0 + a1) + (a2 + a3);
        f  += SS;
        op += OUTP * OUTP;
    }
}

// ------------------------------- launcher ------------------------------------
extern "C" void kernel_launch(void* const* d_in, const int* in_sizes, int n_in,
                              void* d_out, int out_size) {
    const float* p32 = (const float*)d_in[0];
    const float* p16 = (const float*)d_in[1];
    const float* p8  = (const float*)d_in[2];
    // d_in[3] = p4 (unused by the reference forward)
    const float* b32 = (const float*)d_in[4];
    const float* b16 = (const float*)d_in[5];
    const float* b8  = (const float*)d_in[6];
    const float* s32 = (const float*)d_in[7];
    const float* s16 = (const float*)d_in[8];
    const float* s8  = (const float*)d_in[9];
    float* out = (float*)d_out;

    // ONE extra stream + TWO events (R13-proven footprint).
    static cudaStream_t sn = nullptr;      // high-priority: nms
    static cudaEvent_t  ev0, ev1;
    if (sn == nullptr) {
        int loPri, hiPri;
        cudaDeviceGetStreamPriorityRange(&loPri, &hiPri);
        cudaStreamCreateWithPriority(&sn, cudaStreamNonBlocking, hiPri);
        cudaEventCreateWithFlags(&ev0, cudaEventDisableTiming);
        cudaEventCreateWithFlags(&ev1, cudaEventDisableTiming);
        // nms: keys (48KB) + boxes (96KB) = 144KB; roi: 96KB fence
        cudaFuncSetAttribute(nms_kernel,
                             cudaFuncAttributeMaxDynamicSharedMemorySize,
                             (int)((size_t)NBOX * (8 + 16)));
        cudaFuncSetAttribute(roi_kernel,
                             cudaFuncAttributeMaxDynamicSharedMemorySize,
                             ROI_SMEM);
    }
    const size_t NMS_SMEM = (size_t)NBOX * (8 + 16);

    // sentinel init on default stream, then fork to the nms stream
    init_kernel<<<1, 512>>>();
    cudaEventRecord(ev0, 0);
    cudaStreamWaitEvent(sn, ev0, 0);

    // nms on the high-priority stream (6 blocks; signals residency)
    nms_kernel<<<6, NMS_BD, NMS_SMEM, sn>>>(b32, b16, b8, s32, s16, s8);

    // gate (default stream): returns only once all 6 nms blocks are resident,
    // guaranteeing the smem-fenced roi flood cannot exclude nms from the GPU.
    gate_kernel<<<1, 32>>>();

    // roi on the default stream, kk-major order, smem fence
    roi_kernel<<<6144, 224, ROI_SMEM>>>(p32, p16, p8, b32, b16, b8, out);

    // join the nms stream back into the default stream
    cudaEventRecord(ev1, sn);
    cudaStreamWaitEvent(0, ev1, 0);
}

// round 15
// speedup vs baseline: 2.0347x; 1.0428x over previous
#include <cuda_runtime.h>
#include <cstdint>
#include <cstddef>

// ----------------------------------------------------------------------------
// InstanceSegmentationHead, iteration-level pipelined:
//   init -> [hi-pri] nms (6 blocks, signals residency, streams selections)
//        -> [default] gate (waits nms resident) -> roi (kk-major order,
//           96KB smem fence keeps roi off the 6 nms SMs, spin-waits per tile).
// B=2, C=256, N=2048 per source, feature sizes 28/56/112.
// ----------------------------------------------------------------------------

#define NBOX 6144
#define BATCH 2
#define CCH 256
#define KKEEP 64
#define OUTP 14
#define CPB 16              // channels per roi block
#define ROI_SMEM (96 * 1024)   // fence: nms SM has 228-144=84KB free < 96KB

// ---------------- scratch (__device__ globals; no allocation) ---------------
// -2 = not ready (set by init_kernel); -1 = no selection; >=0 = box index
__device__ int g_sel[6][KKEEP];
__device__ int g_ready;     // # of resident nms blocks (reset by init)

// order-preserving float->uint mapping (monotonic)
__device__ __forceinline__ unsigned ford(float f) {
    unsigned u = __float_as_uint(f);
    return (u & 0x80000000u) ? ~u : (u | 0x80000000u);
}

// ------------------------- stage 0: sentinel init ----------------------------
__global__ void init_kernel() {
    int t = threadIdx.x;
    if (t < 6 * KKEEP) ((volatile int*)g_sel)[t] = -2;
    if (t == 6 * KKEEP) *(volatile int*)&g_ready = 0;
}

// ----------------- gate: wait until all 6 nms blocks are resident ------------
__global__ void gate_kernel() {
    if (threadIdx.x == 0) {
        volatile int* vr = &g_ready;
        while (*vr < 6) __nanosleep(200);
    }
}

// --------------------- fused prep + greedy NMS (all levels) ------------------
// 6 blocks: bl = blockIdx.x -> (b = bl/3, level = bl%3+1). Block scans all 6144
// raw boxes, compacts its level into SMEM (key u64 + xyxy float4), then runs
// register-resident NMS, publishing each selection immediately (volatile).
// key = ford(score)<<32 | (8191-j)<<13 | slot  (exact greedy order incl. ties;
// hi/lo u32 split enables REDUX-based argmax).
#define NMS_BD 512
#define NMS_U  12        // 512*12 = 6144 = NBOX

__global__ void __launch_bounds__(NMS_BD, 1) nms_kernel(
    const float* __restrict__ b32, const float* __restrict__ b16,
    const float* __restrict__ b8,
    const float* __restrict__ s32, const float* __restrict__ s16,
    const float* __restrict__ s8) {
    extern __shared__ char smraw[];
    unsigned long long* skey = (unsigned long long*)smraw;           // 48KB
    float4* sbox = (float4*)(smraw + (size_t)NBOX * 8);              // 96KB

    __shared__ unsigned rk_hi[16];
    __shared__ unsigned rk_lo[16];
    __shared__ unsigned long long s_wk;
    __shared__ int                s_n;

    int bl   = blockIdx.x;           // 0..5
    int b    = bl / 3;
    int ltgt = bl - b * 3 + 1;       // target level 1..3
    int tid  = threadIdx.x;
    int lane = tid & 31;
    int wid  = tid >> 5;

    if (tid == 0) { atomicAdd(&g_ready, 1); s_n = 0; }   // signal residency
    __syncthreads();

    // ---- fused prep: scan all boxes, keep this level's ----
    // level = clip(floor(3+log2(sqrt(wh)/224)),1,4) == 1+(s>=112)+(s>=224)+(s>=448)
    // (thresholds are exact powers-of-two ratios of 224; sqrtf kept identical)
    for (int j = tid; j < NBOX; j += NMS_BD) {
        int src = j >> 11;           // 0,1,2
        int jj  = j & 2047;
        const float* bp; const float* sp; float s;
        if (src == 0)      { bp = b32; sp = s32; s = 32.f; }
        else if (src == 1) { bp = b16; sp = s16; s = 16.f; }
        else               { bp = b8;  sp = s8;  s = 8.f;  }
        const float4 bx = *(const float4*)(bp + ((size_t)(b * 2048 + jj)) * 4);
        float sc = sp[(size_t)b * 2048 + jj];

        float sz = sqrtf(__fmul_rn(bx.z, bx.w));
        int lvl = 1 + (sz >= 112.0f) + (sz >= 224.0f) + (sz >= 448.0f);

        if (lvl == ltgt) {
            // scaled xyxy (single-op IEEE rounding, no fma contraction)
            float scx = __fmul_rn(bx.x, s), scy = __fmul_rn(bx.y, s);
            float sw  = __fmul_rn(bx.z, s), sh  = __fmul_rn(bx.w, s);
            float hx  = __fmul_rn(sw, 0.5f), hy = __fmul_rn(sh, 0.5f);
            float x1  = __fsub_rn(scx, hx), y1 = __fsub_rn(scy, hy);
            float x2  = __fadd_rn(scx, hx), y2 = __fadd_rn(scy, hy);
            int pos = atomicAdd(&s_n, 1);
            // higher score wins; ties -> smaller orig index; low bits = slot
            skey[pos] = ((unsigned long long)ford(sc) << 32) |
                        ((unsigned long long)(8191 - j) << 13) |
                        (unsigned long long)pos;
            sbox[pos] = make_float4(x1, y1, x2, y2);
        }
    }
    __syncthreads();
    int n = s_n;

    // ---- register-resident load ----
    unsigned long long key[NMS_U];
    float4             box[NMS_U];
    float              area[NMS_U];
    #pragma unroll
    for (int u = 0; u < NMS_U; ++u) {
        int j = tid + u * NMS_BD;
        key[u]  = 0ull;
        box[u]  = make_float4(0.f, 0.f, 0.f, 0.f);
        area[u] = 0.f;
        if (j < n) {
            key[u] = skey[j];
            float4 bb = sbox[j];
            box[u]  = bb;
            area[u] = __fmul_rn(fmaxf(__fsub_rn(bb.z, bb.x), 0.f),
                                fmaxf(__fsub_rn(bb.w, bb.y), 0.f));
        }
    }
    __syncthreads();

    const float MLO = 2.9802322387695312e-8f;    // 2^-25 = half-ulp of 0.7f

    // initial "winner" suppresses nothing (intersection clamps to 0)
    float4 wb = make_float4(1e30f, 1e30f, 1e30f, 1e30f);

    int it = 0;
    for (; it < KKEEP; ++it) {
        float a = __fmul_rn(fmaxf(__fsub_rn(wb.z, wb.x), 0.f),
                            fmaxf(__fsub_rn(wb.w, wb.y), 0.f));

        unsigned long long bk = 0ull;

        #pragma unroll
        for (int u = 0; u < NMS_U; ++u) {
            if (u * NMS_BD >= n) break;          // uniform: skip unused tail
            // warp-uniform skip of fully-dead 32-slot groups
            unsigned alivem = __ballot_sync(0xFFFFFFFFu, key[u] != 0ull);
            if (!alivem) continue;
            float4 bb = box[u];
            float ix1 = fmaxf(wb.x, bb.x), iy1 = fmaxf(wb.y, bb.y);
            float ix2 = fminf(wb.z, bb.z), iy2 = fminf(wb.w, bb.w);
            float inter = __fmul_rn(fmaxf(__fsub_rn(ix2, ix1), 0.f),
                                    fmaxf(__fsub_rn(iy2, iy1), 0.f));
            float denom = __fadd_rn(__fsub_rn(__fadd_rn(a, area[u]), inter), 1e-9f);
            // suppress <=> rn(inter/denom) > 0.7f <=> inter >= (0.7f+2^-25)*denom
            float dd = __fmaf_rn(-0.7f, denom, inter);
            float tt = __fmul_rn(MLO, denom);    // exact (power of two)
            if (dd >= tt) key[u] = 0ull;         // dead keys can never win
            if (key[u] > bk) bk = key[u];
        }

        // block argmax of key via u32 REDUX split (hi = score, lo = tiebreak)
        unsigned hi = (unsigned)(bk >> 32), lo = (unsigned)bk;
        unsigned m  = __reduce_max_sync(0xFFFFFFFFu, hi);
        unsigned c  = (hi == m) ? lo : 0u;
        unsigned l  = __reduce_max_sync(0xFFFFFFFFu, c);
        if (lane == 0) { rk_hi[wid] = m; rk_lo[wid] = l; }
        __syncthreads();
        if (tid < 32) {
            unsigned h2 = (lane < 16) ? rk_hi[lane] : 0u;
            unsigned l2 = (lane < 16) ? rk_lo[lane] : 0u;
            unsigned m2 = __reduce_max_sync(0xFFFFFFFFu, h2);
            unsigned c2 = (h2 == m2) ? l2 : 0u;
            unsigned lm = __reduce_max_sync(0xFFFFFFFFu, c2);
            if (tid == 0)
                s_wk = ((unsigned long long)m2 << 32) | (unsigned long long)lm;
        }
        __syncthreads();

        unsigned long long wk = s_wk;
        if (wk == 0ull) break;                   // all suppressed -> rest are -1
        wb = sbox[(int)(wk & 8191u)];            // broadcast LDS
        if (tid == 0)                            // publish immediately (volatile)
            ((volatile int*)g_sel)[bl * KKEEP + it] =
                8191 - (int)((wk >> 13) & 8191u);
    }

    for (int j = it + tid; j < KKEEP; j += NMS_BD)
        ((volatile int*)g_sel)[bl * KKEEP + j] = -1;
}

// ------------------------- ROI align (all levels, fused) ---------------------
// 1-D grid of 6144 blocks in kk-MAJOR order: early-dispatched blocks need the
// earliest NMS iterations -> spinners release at the production rate.
// idx -> kk = idx/96; u = (idx%96)/16 -> (b,lvl); cg = (idx%16)*16.
// 96KB dynamic smem (unused) fences roi off the 6 nms SMs.
__global__ void __launch_bounds__(224, 4) roi_kernel(
    const float* __restrict__ p32, const float* __restrict__ p16,
    const float* __restrict__ p8,
    const float* __restrict__ b32, const float* __restrict__ b16,
    const float* __restrict__ b8,
    float* __restrict__ out) {
    extern __shared__ char fence_smem[];   // intentionally unused (SM fence)
    (void)fence_smem;
    __shared__ int s_sel;

    int idx = blockIdx.x;          // 0..6143
    int kk  = idx / 96;
    int r   = idx - kk * 96;
    int u   = r >> 4;              // 0..5 = b*3+lvl
    int b   = (u >= 3) ? 1 : 0;
    int lvl = u - b * 3;
    int k   = lvl * 64 + kk;
    int bk  = b * 192 + k;
    int cg  = (r & 15) * CPB;
    int tid = threadIdx.x;

    // spin for our selection (written exactly once per replay; -2 = not ready)
    if (tid == 0) {
        volatile int* vp = ((volatile int*)g_sel) + (b * 3 + lvl) * KKEEP + kk;
        int v = *vp;
        while (v == -2) { __nanosleep(200); v = *vp; }
        s_sel = v;
    }
    __syncthreads();
    int sel = s_sel;

    float* o = out + (size_t)bk * (CCH * OUTP * OUTP) + (size_t)cg * (OUTP * OUTP);
    float4* o4 = (float4*)o;       // 784B-aligned

    if (sel < 0) {
        float4 z = make_float4(0.f, 0.f, 0.f, 0.f);
        for (int i = tid; i < CPB * 49; i += 224) o4[i] = z;
        return;
    }

    int S = (lvl == 0) ? 28 : (lvl == 1) ? 56 : 112;
    int SS = S * S;
    const float* fbase = ((lvl == 0) ? p32 : (lvl == 1) ? p16 : p8)
                         + ((size_t)b * CCH + cg) * (size_t)SS;

    // recompute the scaled cxcywh box from raw inputs (bit-exact vs the
    // reference's scaled concat); fed into roi_align as x1,y1,x2,y2.
    int src = sel >> 11;
    int jj  = sel & 2047;
    const float* bpp = ((src == 0) ? b32 : (src == 1) ? b16 : b8)
                       + ((size_t)(b * 2048 + jj)) * 4;
    float s = (src == 0) ? 32.f : (src == 1) ? 16.f : 8.f;
    float x1 = __fmul_rn(bpp[0], s);
    float y1 = __fmul_rn(bpp[1], s);
    float x2 = __fmul_rn(bpp[2], s);
    float y2 = __fmul_rn(bpp[3], s);
    float bw = __fdiv_rn(__fsub_rn(x2, x1), 14.0f);
    float bh = __fdiv_rn(__fsub_rn(y2, y1), 14.0f);

    float lim = (float)(S - 1);
    bool xc = (x1 >= lim) && (bw >= 0.f);   // all x-samples clamp to S-1, fx=0
    bool yc = (y1 >= lim) && (bh >= 0.f);   // all y-samples clamp to S-1, fy=0

    // ---- corner path: tile == F[c][S*S-1] exactly ----
    if (xc && yc) {
        int c = tid / 14;                 // 224 = 16*14: c in [0,16), r in [0,14)
        int rr = tid - c * 14;
        float v = __ldg(fbase + (size_t)c * SS + (SS - 1));
        float4 v4 = make_float4(v, v, v, v);
        int base = c * 49;
        #pragma unroll
        for (int i = rr; i < 49; i += 14) o4[base + i] = v4;
        return;
    }

    // ---- x-clamped: every row constant; v depends on (c, oy) only ----
    if (xc) {
        int c  = tid / 14;
        int oy = tid - c * 14;
        const float* f = fbase + (size_t)c * SS;
        float acc = 0.f;
        #pragma unroll
        for (int q = 0; q < 2; ++q) {
            float ty = __fadd_rn((float)oy, q ? 0.75f : 0.25f);
            float cy = __fadd_rn(y1, __fmul_rn(ty, bh));
            cy = fminf(fmaxf(cy, 0.0f), lim);
            float c0 = floorf(cy);
            float fy = __fsub_rn(cy, c0);
            int iy0 = (int)c0;
            int iy1 = min(iy0 + 1, S - 1);
            float g0 = __ldg(f + iy0 * S + (S - 1));
            float g1 = __ldg(f + iy1 * S + (S - 1));
            acc += g0 * (1.0f - fy) + g1 * fy;
        }
        float v = acc * 0.5f;             // mean of 4 samples, pairs equal
        float* op = o + c * 196 + oy * 14;
        #pragma unroll
        for (int i = 0; i < 14; ++i) op[i] = v;
        return;
    }

    // ---- y-clamped: every column constant; v depends on (c, ox) only ----
    if (yc) {
        int c  = tid / 14;
        int ox = tid - c * 14;
        const float* f = fbase + (size_t)c * SS + (size_t)(S - 1) * S;  // last row
        float acc = 0.f;
        #pragma unroll
        for (int q = 0; q < 2; ++q) {
            float tx = __fadd_rn((float)ox, q ? 0.75f : 0.25f);
            float cx = __fadd_rn(x1, __fmul_rn(tx, bw));
            cx = fminf(fmaxf(cx, 0.0f), lim);
            float d0 = floorf(cx);
            float fx = __fsub_rn(cx, d0);
            int ix0 = (int)d0;
            int ix1 = min(ix0 + 1, S - 1);
            float g0 = __ldg(f + ix0);
            float g1 = __ldg(f + ix1);
            acc += g0 * (1.0f - fx) + g1 * fx;
        }
        float v = acc * 0.5f;
        float* op = o + c * 196 + ox;
        #pragma unroll
        for (int i = 0; i < 14; ++i) op[i * 14] = v;
        return;
    }

    // ---- full bilinear path ----
    if (tid >= OUTP * OUTP) return;             // 196 active threads

    int p  = tid;
    int oy = p / OUTP;
    int ox = p - oy * OUTP;

    int   iy0[2], iy1[2], ix0[2], ix1[2];
    float fy[2], fx[2];
    #pragma unroll
    for (int q = 0; q < 2; ++q) {
        float ty = __fadd_rn((float)oy, q ? 0.75f : 0.25f);
        float cy = __fadd_rn(y1, __fmul_rn(ty, bh));
        cy = fminf(fmaxf(cy, 0.0f), lim);
        float c0 = floorf(cy);
        fy[q]  = __fsub_rn(cy, c0);
        iy0[q] = (int)c0;
        iy1[q] = min(iy0[q] + 1, S - 1);

        float tx = __fadd_rn((float)ox, q ? 0.75f : 0.25f);
        float cx = __fadd_rn(x1, __fmul_rn(tx, bw));
        cx = fminf(fmaxf(cx, 0.0f), lim);
        float d0 = floorf(cx);
        fx[q]  = __fsub_rn(cx, d0);
        ix0[q] = (int)d0;
        ix1[q] = min(ix0[q] + 1, S - 1);
    }

    // 16 corner offsets + weights (0.25 mean folded in)
    int   off[16];
    float w[16];
    #pragma unroll
    for (int sy = 0; sy < 2; ++sy) {
        #pragma unroll
        for (int sx = 0; sx < 2; ++sx) {
            int s4 = (sy * 2 + sx) * 4;
            int Y0 = iy0[sy] * S, Y1 = iy1[sy] * S;
            float gy = fy[sy], igy = 1.0f - gy;
            float gx = fx[sx], igx = 1.0f - gx;
            off[s4 + 0] = Y0 + ix0[sx];  w[s4 + 0] = igy * igx * 0.25f;
            off[s4 + 1] = Y0 + ix1[sx];  w[s4 + 1] = igy * gx  * 0.25f;
            off[s4 + 2] = Y1 + ix0[sx];  w[s4 + 2] = gy  * igx * 0.25f;
            off[s4 + 3] = Y1 + ix1[sx];  w[s4 + 3] = gy  * gx  * 0.25f;
        }
    }

    const float* f  = fbase;
    float*       op = o + p;
    #pragma unroll 2
    for (int c = 0; c < CPB; ++c) {
        float a0 = 0.f, a1 = 0.f, a2 = 0.f, a3 = 0.f;
        #pragma unroll
        for (int i = 0; i < 4; ++i) {
            a0 = fmaf(__ldg(f + off[4 * i + 0]), w[4 * i + 0], a0);
            a1 = fmaf(__ldg(f + off[4 * i + 1]), w[4 * i + 1], a1);
            a2 = fmaf(__ldg(f + off[4 * i + 2]), w[4 * i + 2], a2);
            a3 = fmaf(__ldg(f + off[4 * i + 3]), w[4 * i + 3], a3);
        }
        *op = (a0 + a1) + (a2 + a3);
        f  += SS;
        op += OUTP * OUTP;
    }
}

// ------------------------------- launcher ------------------------------------
extern "C" void kernel_launch(void* const* d_in, const int* in_sizes, int n_in,
                              void* d_out, int out_size) {
    const float* p32 = (const float*)d_in[0];
    const float* p16 = (const float*)d_in[1];
    const float* p8  = (const float*)d_in[2];
    // d_in[3] = p4 (unused by the reference forward)
    const float* b32 = (const float*)d_in[4];
    const float* b16 = (const float*)d_in[5];
    const float* b8  = (const float*)d_in[6];
    const float* s32 = (const float*)d_in[7];
    const float* s16 = (const float*)d_in[8];
    const float* s8  = (const float*)d_in[9];
    float* out = (float*)d_out;

    // ONE extra stream + TWO events (R13/R14-proven footprint).
    static cudaStream_t sn = nullptr;      // high-priority: nms
    static cudaEvent_t  ev0, ev1;
    if (sn == nullptr) {
        int loPri, hiPri;
        cudaDeviceGetStreamPriorityRange(&loPri, &hiPri);
        cudaStreamCreateWithPriority(&sn, cudaStreamNonBlocking, hiPri);
        cudaEventCreateWithFlags(&ev0, cudaEventDisableTiming);
        cudaEventCreateWithFlags(&ev1, cudaEventDisableTiming);
        // nms: keys (48KB) + boxes (96KB) = 144KB; roi: 96KB fence
        cudaFuncSetAttribute(nms_kernel,
                             cudaFuncAttributeMaxDynamicSharedMemorySize,
                             (int)((size_t)NBOX * (8 + 16)));
        cudaFuncSetAttribute(roi_kernel,
                             cudaFuncAttributeMaxDynamicSharedMemorySize,
                             ROI_SMEM);
    }
    const size_t NMS_SMEM = (size_t)NBOX * (8 + 16);

    // sentinel init on default stream, then fork to the nms stream
    init_kernel<<<1, 512>>>();
    cudaEventRecord(ev0, 0);
    cudaStreamWaitEvent(sn, ev0, 0);

    // nms on the high-priority stream (6 blocks; signals residency)
    nms_kernel<<<6, NMS_BD, NMS_SMEM, sn>>>(b32, b16, b8, s32, s16, s8);

    // gate (default stream): returns only once all 6 nms blocks are resident,
    // guaranteeing the smem-fenced roi flood cannot exclude nms from the GPU.
    gate_kernel<<<1, 32>>>();

    // roi on the default stream, kk-major order, smem fence
    roi_kernel<<<6144, 224, ROI_SMEM>>>(p32, p16, p8, b32, b16, b8, out);

    // join the nms stream back into the default stream
    cudaEventRecord(ev1, sn);
    cudaStreamWaitEvent(0, ev1, 0);
}

// round 16
// speedup vs baseline: 2.1772x; 1.0700x over previous
#include <cuda_runtime.h>
#include <cstdint>
#include <cstddef>

// ----------------------------------------------------------------------------
// InstanceSegmentationHead, iteration-level pipelined:
//   init -> [hi-pri] nms (6 blocks, signals residency, streams selections)
//        -> [default] gate (waits nms resident) -> roi (kk-major order,
//           96KB smem fence keeps roi off the 6 nms SMs, spin-waits per tile).
// NMS inner loop: ONE barrier/iteration (parity-buffered partials, REDUX
// final stage computed redundantly by every warp).
// B=2, C=256, N=2048 per source, feature sizes 28/56/112.
// ----------------------------------------------------------------------------

#define NBOX 6144
#define BATCH 2
#define CCH 256
#define KKEEP 64
#define OUTP 14
#define CPB 16              // channels per roi block
#define ROI_SMEM (96 * 1024)   // fence: nms SM has 228-144=84KB free < 96KB

// ---------------- scratch (__device__ globals; no allocation) ---------------
// -2 = not ready (set by init_kernel); -1 = no selection; >=0 = box index
__device__ int g_sel[6][KKEEP];
__device__ int g_ready;     // # of resident nms blocks (reset by init)

// order-preserving float->uint mapping (monotonic)
__device__ __forceinline__ unsigned ford(float f) {
    unsigned u = __float_as_uint(f);
    return (u & 0x80000000u) ? ~u : (u | 0x80000000u);
}

// ------------------------- stage 0: sentinel init ----------------------------
__global__ void init_kernel() {
    int t = threadIdx.x;
    if (t < 6 * KKEEP) ((volatile int*)g_sel)[t] = -2;
    if (t == 6 * KKEEP) *(volatile int*)&g_ready = 0;
}

// ----------------- gate: wait until all 6 nms blocks are resident ------------
__global__ void gate_kernel() {
    if (threadIdx.x == 0) {
        volatile int* vr = &g_ready;
        while (*vr < 6) __nanosleep(200);
    }
}

// --------------------- fused prep + greedy NMS (all levels) ------------------
// 6 blocks: bl = blockIdx.x -> (b = bl/3, level = bl%3+1). Block scans all 6144
// raw boxes, compacts its level into SMEM (key u64 + xyxy float4), then runs
// register-resident NMS, publishing each selection immediately (volatile).
// key = ford(score)<<32 | (8191-j)<<13 | slot  (exact greedy order incl. ties;
// hi/lo u32 split enables REDUX-based argmax).
#define NMS_BD 512
#define NMS_U  12        // 512*12 = 6144 = NBOX

__global__ void __launch_bounds__(NMS_BD, 1) nms_kernel(
    const float* __restrict__ b32, const float* __restrict__ b16,
    const float* __restrict__ b8,
    const float* __restrict__ s32, const float* __restrict__ s16,
    const float* __restrict__ s8) {
    extern __shared__ char smraw[];
    unsigned long long* skey = (unsigned long long*)smraw;           // 48KB
    float4* sbox = (float4*)(smraw + (size_t)NBOX * 8);              // 96KB

    __shared__ unsigned rk_hi[2][16];    // parity double-buffered partials
    __shared__ unsigned rk_lo[2][16];
    __shared__ int      s_n;

    int bl   = blockIdx.x;           // 0..5
    int b    = bl / 3;
    int ltgt = bl - b * 3 + 1;       // target level 1..3
    int tid  = threadIdx.x;
    int lane = tid & 31;
    int wid  = tid >> 5;

    if (tid == 0) { atomicAdd(&g_ready, 1); s_n = 0; }   // signal residency
    __syncthreads();

    // ---- fused prep: scan all boxes, keep this level's ----
    // level = clip(floor(3+log2(sqrt(wh)/224)),1,4) == 1+(s>=112)+(s>=224)+(s>=448)
    // (thresholds are exact powers-of-two ratios of 224; sqrtf kept identical)
    for (int j = tid; j < NBOX; j += NMS_BD) {
        int src = j >> 11;           // 0,1,2
        int jj  = j & 2047;
        const float* bp; const float* sp; float s;
        if (src == 0)      { bp = b32; sp = s32; s = 32.f; }
        else if (src == 1) { bp = b16; sp = s16; s = 16.f; }
        else               { bp = b8;  sp = s8;  s = 8.f;  }
        const float4 bx = *(const float4*)(bp + ((size_t)(b * 2048 + jj)) * 4);
        float sc = sp[(size_t)b * 2048 + jj];

        float sz = sqrtf(__fmul_rn(bx.z, bx.w));
        int lvl = 1 + (sz >= 112.0f) + (sz >= 224.0f) + (sz >= 448.0f);

        if (lvl == ltgt) {
            // scaled xyxy (single-op IEEE rounding, no fma contraction)
            float scx = __fmul_rn(bx.x, s), scy = __fmul_rn(bx.y, s);
            float sw  = __fmul_rn(bx.z, s), sh  = __fmul_rn(bx.w, s);
            float hx  = __fmul_rn(sw, 0.5f), hy = __fmul_rn(sh, 0.5f);
            float x1  = __fsub_rn(scx, hx), y1 = __fsub_rn(scy, hy);
            float x2  = __fadd_rn(scx, hx), y2 = __fadd_rn(scy, hy);
            int pos = atomicAdd(&s_n, 1);
            // higher score wins; ties -> smaller orig index; low bits = slot
            skey[pos] = ((unsigned long long)ford(sc) << 32) |
                        ((unsigned long long)(8191 - j) << 13) |
                        (unsigned long long)pos;
            sbox[pos] = make_float4(x1, y1, x2, y2);
        }
    }
    __syncthreads();
    int n = s_n;

    // ---- register-resident load ----
    unsigned long long key[NMS_U];
    float4             box[NMS_U];
    float              area[NMS_U];
    #pragma unroll
    for (int u = 0; u < NMS_U; ++u) {
        int j = tid + u * NMS_BD;
        key[u]  = 0ull;
        box[u]  = make_float4(0.f, 0.f, 0.f, 0.f);
        area[u] = 0.f;
        if (j < n) {
            key[u] = skey[j];
            float4 bb = sbox[j];
            box[u]  = bb;
            area[u] = __fmul_rn(fmaxf(__fsub_rn(bb.z, bb.x), 0.f),
                                fmaxf(__fsub_rn(bb.w, bb.y), 0.f));
        }
    }
    __syncthreads();

    const float MLO = 2.9802322387695312e-8f;    // 2^-25 = half-ulp of 0.7f

    // initial "winner" suppresses nothing (intersection clamps to 0)
    float4 wb = make_float4(1e30f, 1e30f, 1e30f, 1e30f);

    int it = 0;
    for (; it < KKEEP; ++it) {
        int par = it & 1;
        float a = __fmul_rn(fmaxf(__fsub_rn(wb.z, wb.x), 0.f),
                            fmaxf(__fsub_rn(wb.w, wb.y), 0.f));

        unsigned long long bk = 0ull;

        #pragma unroll
        for (int u = 0; u < NMS_U; ++u) {
            if (u * NMS_BD >= n) break;          // uniform: skip unused tail
            float4 bb = box[u];
            float ix1 = fmaxf(wb.x, bb.x), iy1 = fmaxf(wb.y, bb.y);
            float ix2 = fminf(wb.z, bb.z), iy2 = fminf(wb.w, bb.w);
            float inter = __fmul_rn(fmaxf(__fsub_rn(ix2, ix1), 0.f),
                                    fmaxf(__fsub_rn(iy2, iy1), 0.f));
            float denom = __fadd_rn(__fsub_rn(__fadd_rn(a, area[u]), inter), 1e-9f);
            // suppress <=> rn(inter/denom) > 0.7f <=> inter >= (0.7f+2^-25)*denom
            float dd = __fmaf_rn(-0.7f, denom, inter);
            float tt = __fmul_rn(MLO, denom);    // exact (power of two)
            if (dd >= tt) key[u] = 0ull;         // dead keys can never win
            if (key[u] > bk) bk = key[u];
        }

        // warp argmax via u32 REDUX split (hi = score, lo = tiebreak+slot)
        unsigned hi = (unsigned)(bk >> 32), lo = (unsigned)bk;
        unsigned m  = __reduce_max_sync(0xFFFFFFFFu, hi);
        unsigned c  = (hi == m) ? lo : 0u;
        unsigned l  = __reduce_max_sync(0xFFFFFFFFu, c);
        if (lane == 0) { rk_hi[par][wid] = m; rk_lo[par][wid] = l; }
        __syncthreads();                         // the ONLY barrier per iter

        // final stage computed redundantly by EVERY warp (parity buffer makes
        // next iteration's partial writes race-free without a second barrier)
        unsigned h2 = (lane < 16) ? rk_hi[par][lane] : 0u;
        unsigned l2 = (lane < 16) ? rk_lo[par][lane] : 0u;
        unsigned m2 = __reduce_max_sync(0xFFFFFFFFu, h2);
        unsigned c2 = (h2 == m2) ? l2 : 0u;
        unsigned lm = __reduce_max_sync(0xFFFFFFFFu, c2);
        unsigned long long wk =
            ((unsigned long long)m2 << 32) | (unsigned long long)lm;

        if (wk == 0ull) break;                   // all suppressed -> rest are -1
        wb = sbox[(int)(wk & 8191u)];            // broadcast LDS (per warp)
        if (tid == 0)                            // publish immediately (volatile)
            ((volatile int*)g_sel)[bl * KKEEP + it] =
                8191 - (int)((wk >> 13) & 8191u);
    }

    for (int j = it + tid; j < KKEEP; j += NMS_BD)
        ((volatile int*)g_sel)[bl * KKEEP + j] = -1;
}

// ------------------------- ROI align (all levels, fused) ---------------------
// 1-D grid of 6144 blocks in kk-MAJOR order: early-dispatched blocks need the
// earliest NMS iterations -> spinners release at the production rate.
// idx -> kk = idx/96; u = (idx%96)/16 -> (b,lvl); cg = (idx%16)*16.
// 96KB dynamic smem (unused) fences roi off the 6 nms SMs.
__global__ void __launch_bounds__(224, 4) roi_kernel(
    const float* __restrict__ p32, const float* __restrict__ p16,
    const float* __restrict__ p8,
    const float* __restrict__ b32, const float* __restrict__ b16,
    const float* __restrict__ b8,
    float* __restrict__ out) {
    extern __shared__ char fence_smem[];   // intentionally unused (SM fence)
    (void)fence_smem;
    __shared__ int s_sel;

    int idx = blockIdx.x;          // 0..6143
    int kk  = idx / 96;
    int r   = idx - kk * 96;
    int u   = r >> 4;              // 0..5 = b*3+lvl
    int b   = (u >= 3) ? 1 : 0;
    int lvl = u - b * 3;
    int k   = lvl * 64 + kk;
    int bk  = b * 192 + k;
    int cg  = (r & 15) * CPB;
    int tid = threadIdx.x;

    // spin for our selection (written exactly once per replay; -2 = not ready)
    if (tid == 0) {
        volatile int* vp = ((volatile int*)g_sel) + (b * 3 + lvl) * KKEEP + kk;
        int v = *vp;
        while (v == -2) { __nanosleep(200); v = *vp; }
        s_sel = v;
    }
    __syncthreads();
    int sel = s_sel;

    float* o = out + (size_t)bk * (CCH * OUTP * OUTP) + (size_t)cg * (OUTP * OUTP);
    float4* o4 = (float4*)o;       // 784B-aligned

    if (sel < 0) {
        float4 z = make_float4(0.f, 0.f, 0.f, 0.f);
        for (int i = tid; i < CPB * 49; i += 224) o4[i] = z;
        return;
    }

    int S = (lvl == 0) ? 28 : (lvl == 1) ? 56 : 112;
    int SS = S * S;
    const float* fbase = ((lvl == 0) ? p32 : (lvl == 1) ? p16 : p8)
                         + ((size_t)b * CCH + cg) * (size_t)SS;

    // recompute the scaled cxcywh box from raw inputs (bit-exact vs the
    // reference's scaled concat); fed into roi_align as x1,y1,x2,y2.
    int src = sel >> 11;
    int jj  = sel & 2047;
    const float* bpp = ((src == 0) ? b32 : (src == 1) ? b16 : b8)
                       + ((size_t)(b * 2048 + jj)) * 4;
    float s = (src == 0) ? 32.f : (src == 1) ? 16.f : 8.f;
    float x1 = __fmul_rn(bpp[0], s);
    float y1 = __fmul_rn(bpp[1], s);
    float x2 = __fmul_rn(bpp[2], s);
    float y2 = __fmul_rn(bpp[3], s);
    float bw = __fdiv_rn(__fsub_rn(x2, x1), 14.0f);
    float bh = __fdiv_rn(__fsub_rn(y2, y1), 14.0f);

    float lim = (float)(S - 1);
    bool xc = (x1 >= lim) && (bw >= 0.f);   // all x-samples clamp to S-1, fx=0
    bool yc = (y1 >= lim) && (bh >= 0.f);   // all y-samples clamp to S-1, fy=0

    // ---- corner path: tile == F[c][S*S-1] exactly ----
    if (xc && yc) {
        int c = tid / 14;                 // 224 = 16*14: c in [0,16), r in [0,14)
        int rr = tid - c * 14;
        float v = __ldg(fbase + (size_t)c * SS + (SS - 1));
        float4 v4 = make_float4(v, v, v, v);
        int base = c * 49;
        #pragma unroll
        for (int i = rr; i < 49; i += 14) o4[base + i] = v4;
        return;
    }

    // ---- x-clamped: every row constant; v depends on (c, oy) only ----
    if (xc) {
        int c  = tid / 14;
        int oy = tid - c * 14;
        const float* f = fbase + (size_t)c * SS;
        float acc = 0.f;
        #pragma unroll
        for (int q = 0; q < 2; ++q) {
            float ty = __fadd_rn((float)oy, q ? 0.75f : 0.25f);
            float cy = __fadd_rn(y1, __fmul_rn(ty, bh));
            cy = fminf(fmaxf(cy, 0.0f), lim);
            float c0 = floorf(cy);
            float fy = __fsub_rn(cy, c0);
            int iy0 = (int)c0;
            int iy1 = min(iy0 + 1, S - 1);
            float g0 = __ldg(f + iy0 * S + (S - 1));
            float g1 = __ldg(f + iy1 * S + (S - 1));
            acc += g0 * (1.0f - fy) + g1 * fy;
        }
        float v = acc * 0.5f;             // mean of 4 samples, pairs equal
        float* op = o + c * 196 + oy * 14;
        #pragma unroll
        for (int i = 0; i < 14; ++i) op[i] = v;
        return;
    }

    // ---- y-clamped: every column constant; v depends on (c, ox) only ----
    if (yc) {
        int c  = tid / 14;
        int ox = tid - c * 14;
        const float* f = fbase + (size_t)c * SS + (size_t)(S - 1) * S;  // last row
        float acc = 0.f;
        #pragma unroll
        for (int q = 0; q < 2; ++q) {
            float tx = __fadd_rn((float)ox, q ? 0.75f : 0.25f);
            float cx = __fadd_rn(x1, __fmul_rn(tx, bw));
            cx = fminf(fmaxf(cx, 0.0f), lim);
            float d0 = floorf(cx);
            float fx = __fsub_rn(cx, d0);
            int ix0 = (int)d0;
            int ix1 = min(ix0 + 1, S - 1);
            float g0 = __ldg(f + ix0);
            float g1 = __ldg(f + ix1);
            acc += g0 * (1.0f - fx) + g1 * fx;
        }
        float v = acc * 0.5f;
        float* op = o + c * 196 + ox;
        #pragma unroll
        for (int i = 0; i < 14; ++i) op[i * 14] = v;
        return;
    }

    // ---- full bilinear path ----
    if (tid >= OUTP * OUTP) return;             // 196 active threads

    int p  = tid;
    int oy = p / OUTP;
    int ox = p - oy * OUTP;

    int   iy0[2], iy1[2], ix0[2], ix1[2];
    float fy[2], fx[2];
    #pragma unroll
    for (int q = 0; q < 2; ++q) {
        float ty = __fadd_rn((float)oy, q ? 0.75f : 0.25f);
        float cy = __fadd_rn(y1, __fmul_rn(ty, bh));
        cy = fminf(fmaxf(cy, 0.0f), lim);
        float c0 = floorf(cy);
        fy[q]  = __fsub_rn(cy, c0);
        iy0[q] = (int)c0;
        iy1[q] = min(iy0[q] + 1, S - 1);

        float tx = __fadd_rn((float)ox, q ? 0.75f : 0.25f);
        float cx = __fadd_rn(x1, __fmul_rn(tx, bw));
        cx = fminf(fmaxf(cx, 0.0f), lim);
        float d0 = floorf(cx);
        fx[q]  = __fsub_rn(cx, d0);
        ix0[q] = (int)d0;
        ix1[q] = min(ix0[q] + 1, S - 1);
    }

    // 16 corner offsets + weights (0.25 mean folded in)
    int   off[16];
    float w[16];
    #pragma unroll
    for (int sy = 0; sy < 2; ++sy) {
        #pragma unroll
        for (int sx = 0; sx < 2; ++sx) {
            int s4 = (sy * 2 + sx) * 4;
            int Y0 = iy0[sy] * S, Y1 = iy1[sy] * S;
            float gy = fy[sy], igy = 1.0f - gy;
            float gx = fx[sx], igx = 1.0f - gx;
            off[s4 + 0] = Y0 + ix0[sx];  w[s4 + 0] = igy * igx * 0.25f;
            off[s4 + 1] = Y0 + ix1[sx];  w[s4 + 1] = igy * gx  * 0.25f;
            off[s4 + 2] = Y1 + ix0[sx];  w[s4 + 2] = gy  * igx * 0.25f;
            off[s4 + 3] = Y1 + ix1[sx];  w[s4 + 3] = gy  * gx  * 0.25f;
        }
    }

    const float* f  = fbase;
    float*       op = o + p;
    #pragma unroll 2
    for (int c = 0; c < CPB; ++c) {
        float a0 = 0.f, a1 = 0.f, a2 = 0.f, a3 = 0.f;
        #pragma unroll
        for (int i = 0; i < 4; ++i) {
            a0 = fmaf(__ldg(f + off[4 * i + 0]), w[4 * i + 0], a0);
            a1 = fmaf(__ldg(f + off[4 * i + 1]), w[4 * i + 1], a1);
            a2 = fmaf(__ldg(f + off[4 * i + 2]), w[4 * i + 2], a2);
            a3 = fmaf(__ldg(f + off[4 * i + 3]), w[4 * i + 3], a3);
        }
        *op = (a0 + a1) + (a2 + a3);
        f  += SS;
        op += OUTP * OUTP;
    }
}

// ------------------------------- launcher ------------------------------------
extern "C" void kernel_launch(void* const* d_in, const int* in_sizes, int n_in,
                              void* d_out, int out_size) {
    const float* p32 = (const float*)d_in[0];
    const float* p16 = (const float*)d_in[1];
    const float* p8  = (const float*)d_in[2];
    // d_in[3] = p4 (unused by the reference forward)
    const float* b32 = (const float*)d_in[4];
    const float* b16 = (const float*)d_in[5];
    const float* b8  = (const float*)d_in[6];
    const float* s32 = (const float*)d_in[7];
    const float* s16 = (const float*)d_in[8];
    const float* s8  = (const float*)d_in[9];
    float* out = (float*)d_out;

    // ONE extra stream + TWO events (R13/R14/R15-proven footprint).
    static cudaStream_t sn = nullptr;      // high-priority: nms
    static cudaEvent_t  ev0, ev1;
    if (sn == nullptr) {
        int loPri, hiPri;
        cudaDeviceGetStreamPriorityRange(&loPri, &hiPri);
        cudaStreamCreateWithPriority(&sn, cudaStreamNonBlocking, hiPri);
        cudaEventCreateWithFlags(&ev0, cudaEventDisableTiming);
        cudaEventCreateWithFlags(&ev1, cudaEventDisableTiming);
        // nms: keys (48KB) + boxes (96KB) = 144KB; roi: 96KB fence
        cudaFuncSetAttribute(nms_kernel,
                             cudaFuncAttributeMaxDynamicSharedMemorySize,
                             (int)((size_t)NBOX * (8 + 16)));
        cudaFuncSetAttribute(roi_kernel,
                             cudaFuncAttributeMaxDynamicSharedMemorySize,
                             ROI_SMEM);
    }
    const size_t NMS_SMEM = (size_t)NBOX * (8 + 16);

    // sentinel init on default stream, then fork to the nms stream
    init_kernel<<<1, 512>>>();
    cudaEventRecord(ev0, 0);
    cudaStreamWaitEvent(sn, ev0, 0);

    // nms on the high-priority stream (6 blocks; signals residency)
    nms_kernel<<<6, NMS_BD, NMS_SMEM, sn>>>(b32, b16, b8, s32, s16, s8);

    // gate (default stream): returns only once all 6 nms blocks are resident,
    // guaranteeing the smem-fenced roi flood cannot exclude nms from the GPU.
    gate_kernel<<<1, 32>>>();

    // roi on the default stream, kk-major order, smem fence
    roi_kernel<<<6144, 224, ROI_SMEM>>>(p32, p16, p8, b32, b16, b8, out);

    // join the nms stream back into the default stream
    cudaEventRecord(ev1, sn);
    cudaStreamWaitEvent(0, ev1, 0);
}

// round 17
// speedup vs baseline: 2.1783x; 1.0005x over previous
#include <cuda_runtime.h>
#include <cstdint>
#include <cstddef>

// ----------------------------------------------------------------------------
// InstanceSegmentationHead, iteration-level pipelined:
//   [hi-pri] nms (6 blocks; SELF-initializes its g_sel row, signals residency,
//            streams selections)  ||  [default] gate (waits residency, resets
//            g_ready) -> roi (kk-major order, 96KB smem fence, spin-per-tile).
// NMS inner loop: ONE barrier/iteration (parity-buffered partials, REDUX
// final stage computed redundantly by every warp).
// B=2, C=256, N=2048 per source, feature sizes 28/56/112.
// ----------------------------------------------------------------------------

#define NBOX 6144
#define BATCH 2
#define CCH 256
#define KKEEP 64
#define OUTP 14
#define CPB 16              // channels per roi block
#define ROI_SMEM (96 * 1024)   // fence: nms SM has 228-144=84KB free < 96KB

// ---------------- scratch (__device__ globals; no allocation) ---------------
// -2 = not ready (set by the owning nms block); -1 = none; >=0 = box index
__device__ int g_sel[6][KKEEP];
__device__ int g_ready;     // # resident nms blocks (gate resets to 0)

// order-preserving float->uint mapping (monotonic)
__device__ __forceinline__ unsigned ford(float f) {
    unsigned u = __float_as_uint(f);
    return (u & 0x80000000u) ? ~u : (u | 0x80000000u);
}

// ------- gate: wait until all 6 nms blocks initialized + resident, reset -----
__global__ void gate_kernel() {
    if (threadIdx.x == 0) {
        volatile int* vr = &g_ready;
        while (*vr < 6) __nanosleep(200);
        *vr = 0;                       // self-reset for the next replay
    }
}

// --------------------- fused prep + greedy NMS (all levels) ------------------
// 6 blocks: bl = blockIdx.x -> (b = bl/3, level = bl%3+1). Block initializes
// its own g_sel row to -2, signals residency, scans all 6144 raw boxes,
// compacts its level into SMEM (key u64 + xyxy float4), then runs
// register-resident NMS, publishing each selection immediately (volatile).
// key = ford(score)<<32 | (8191-j)<<13 | slot  (exact greedy order incl. ties;
// hi/lo u32 split enables REDUX-based argmax).
#define NMS_BD 512
#define NMS_U  12        // 512*12 = 6144 = NBOX

__global__ void __launch_bounds__(NMS_BD, 1) nms_kernel(
    const float* __restrict__ b32, const float* __restrict__ b16,
    const float* __restrict__ b8,
    const float* __restrict__ s32, const float* __restrict__ s16,
    const float* __restrict__ s8) {
    extern __shared__ char smraw[];
    unsigned long long* skey = (unsigned long long*)smraw;           // 48KB
    float4* sbox = (float4*)(smraw + (size_t)NBOX * 8);              // 96KB

    __shared__ unsigned rk_hi[2][16];    // parity double-buffered partials
    __shared__ unsigned rk_lo[2][16];
    __shared__ int      s_n;

    int bl   = blockIdx.x;           // 0..5
    int b    = bl / 3;
    int ltgt = bl - b * 3 + 1;       // target level 1..3
    int tid  = threadIdx.x;
    int lane = tid & 31;
    int wid  = tid >> 5;

    // ---- self-init of this block's g_sel row, then residency signal ----
    // Sentinels must be device-visible BEFORE g_ready reaches 6 (gate releases
    // the roi flood only then): store -2, fence, sync, then atomicAdd.
    if (tid < KKEEP) {
        ((volatile int*)g_sel)[bl * KKEEP + tid] = -2;
        __threadfence();
    }
    if (tid == 0) s_n = 0;
    __syncthreads();
    if (tid == 0) atomicAdd(&g_ready, 1);

    // ---- fused prep: scan all boxes, keep this level's ----
    // level = clip(floor(3+log2(sqrt(wh)/224)),1,4) == 1+(s>=112)+(s>=224)+(s>=448)
    // (thresholds are exact powers-of-two ratios of 224; sqrtf kept identical)
    for (int j = tid; j < NBOX; j += NMS_BD) {
        int src = j >> 11;           // 0,1,2
        int jj  = j & 2047;
        const float* bp; const float* sp; float s;
        if (src == 0)      { bp = b32; sp = s32; s = 32.f; }
        else if (src == 1) { bp = b16; sp = s16; s = 16.f; }
        else               { bp = b8;  sp = s8;  s = 8.f;  }
        const float4 bx = *(const float4*)(bp + ((size_t)(b * 2048 + jj)) * 4);
        float sc = sp[(size_t)b * 2048 + jj];

        float sz = sqrtf(__fmul_rn(bx.z, bx.w));
        int lvl = 1 + (sz >= 112.0f) + (sz >= 224.0f) + (sz >= 448.0f);

        if (lvl == ltgt) {
            // scaled xyxy (single-op IEEE rounding, no fma contraction)
            float scx = __fmul_rn(bx.x, s), scy = __fmul_rn(bx.y, s);
            float sw  = __fmul_rn(bx.z, s), sh  = __fmul_rn(bx.w, s);
            float hx  = __fmul_rn(sw, 0.5f), hy = __fmul_rn(sh, 0.5f);
            float x1  = __fsub_rn(scx, hx), y1 = __fsub_rn(scy, hy);
            float x2  = __fadd_rn(scx, hx), y2 = __fadd_rn(scy, hy);
            int pos = atomicAdd(&s_n, 1);
            // higher score wins; ties -> smaller orig index; low bits = slot
            skey[pos] = ((unsigned long long)ford(sc) << 32) |
                        ((unsigned long long)(8191 - j) << 13) |
                        (unsigned long long)pos;
            sbox[pos] = make_float4(x1, y1, x2, y2);
        }
    }
    __syncthreads();
    int n = s_n;

    // ---- register-resident load ----
    unsigned long long key[NMS_U];
    float4             box[NMS_U];
    float              area[NMS_U];
    #pragma unroll
    for (int u = 0; u < NMS_U; ++u) {
        int j = tid + u * NMS_BD;
        key[u]  = 0ull;
        box[u]  = make_float4(0.f, 0.f, 0.f, 0.f);
        area[u] = 0.f;
        if (j < n) {
            key[u] = skey[j];
            float4 bb = sbox[j];
            box[u]  = bb;
            area[u] = __fmul_rn(fmaxf(__fsub_rn(bb.z, bb.x), 0.f),
                                fmaxf(__fsub_rn(bb.w, bb.y), 0.f));
        }
    }
    __syncthreads();

    const float MLO = 2.9802322387695312e-8f;    // 2^-25 = half-ulp of 0.7f

    // initial "winner" suppresses nothing (intersection clamps to 0)
    float4 wb = make_float4(1e30f, 1e30f, 1e30f, 1e30f);

    int it = 0;
    for (; it < KKEEP; ++it) {
        int par = it & 1;
        float a = __fmul_rn(fmaxf(__fsub_rn(wb.z, wb.x), 0.f),
                            fmaxf(__fsub_rn(wb.w, wb.y), 0.f));

        unsigned long long bk = 0ull;

        #pragma unroll
        for (int u = 0; u < NMS_U; ++u) {
            if (u * NMS_BD >= n) break;          // uniform: skip unused tail
            float4 bb = box[u];
            float ix1 = fmaxf(wb.x, bb.x), iy1 = fmaxf(wb.y, bb.y);
            float ix2 = fminf(wb.z, bb.z), iy2 = fminf(wb.w, bb.w);
            float inter = __fmul_rn(fmaxf(__fsub_rn(ix2, ix1), 0.f),
                                    fmaxf(__fsub_rn(iy2, iy1), 0.f));
            float denom = __fadd_rn(__fsub_rn(__fadd_rn(a, area[u]), inter), 1e-9f);
            // suppress <=> rn(inter/denom) > 0.7f <=> inter >= (0.7f+2^-25)*denom
            float dd = __fmaf_rn(-0.7f, denom, inter);
            float tt = __fmul_rn(MLO, denom);    // exact (power of two)
            if (dd >= tt) key[u] = 0ull;         // dead keys can never win
            if (key[u] > bk) bk = key[u];
        }

        // warp argmax via u32 REDUX split (hi = score, lo = tiebreak+slot)
        unsigned hi = (unsigned)(bk >> 32), lo = (unsigned)bk;
        unsigned m  = __reduce_max_sync(0xFFFFFFFFu, hi);
        unsigned c  = (hi == m) ? lo : 0u;
        unsigned l  = __reduce_max_sync(0xFFFFFFFFu, c);
        if (lane == 0) { rk_hi[par][wid] = m; rk_lo[par][wid] = l; }
        __syncthreads();                         // the ONLY barrier per iter

        // final stage computed redundantly by EVERY warp (parity buffer makes
        // next iteration's partial writes race-free without a second barrier)
        unsigned h2 = (lane < 16) ? rk_hi[par][lane] : 0u;
        unsigned l2 = (lane < 16) ? rk_lo[par][lane] : 0u;
        unsigned m2 = __reduce_max_sync(0xFFFFFFFFu, h2);
        unsigned c2 = (h2 == m2) ? l2 : 0u;
        unsigned lm = __reduce_max_sync(0xFFFFFFFFu, c2);
        unsigned long long wk =
            ((unsigned long long)m2 << 32) | (unsigned long long)lm;

        if (wk == 0ull) break;                   // all suppressed -> rest are -1
        wb = sbox[(int)(wk & 8191u)];            // broadcast LDS (per warp)
        if (tid == 0)                            // publish immediately (volatile)
            ((volatile int*)g_sel)[bl * KKEEP + it] =
                8191 - (int)((wk >> 13) & 8191u);
    }

    for (int j = it + tid; j < KKEEP; j += NMS_BD)
        ((volatile int*)g_sel)[bl * KKEEP + j] = -1;
}

// ------------------------- ROI align (all levels, fused) ---------------------
// 1-D grid of 6144 blocks in kk-MAJOR order: early-dispatched blocks need the
// earliest NMS iterations -> spinners release at the production rate.
// idx -> kk = idx/96; u = (idx%96)/16 -> (b,lvl); cg = (idx%16)*16.
// 96KB dynamic smem (unused) fences roi off the 6 nms SMs.
__global__ void __launch_bounds__(224, 4) roi_kernel(
    const float* __restrict__ p32, const float* __restrict__ p16,
    const float* __restrict__ p8,
    const float* __restrict__ b32, const float* __restrict__ b16,
    const float* __restrict__ b8,
    float* __restrict__ out) {
    extern __shared__ char fence_smem[];   // intentionally unused (SM fence)
    (void)fence_smem;
    __shared__ int s_sel;

    int idx = blockIdx.x;          // 0..6143
    int kk  = idx / 96;
    int r   = idx - kk * 96;
    int u   = r >> 4;              // 0..5 = b*3+lvl
    int b   = (u >= 3) ? 1 : 0;
    int lvl = u - b * 3;
    int k   = lvl * 64 + kk;
    int bk  = b * 192 + k;
    int cg  = (r & 15) * CPB;
    int tid = threadIdx.x;

    // spin for our selection (written exactly once per replay; -2 = not ready)
    if (tid == 0) {
        volatile int* vp = ((volatile int*)g_sel) + (b * 3 + lvl) * KKEEP + kk;
        int v = *vp;
        while (v == -2) { __nanosleep(200); v = *vp; }
        s_sel = v;
    }
    __syncthreads();
    int sel = s_sel;

    float* o = out + (size_t)bk * (CCH * OUTP * OUTP) + (size_t)cg * (OUTP * OUTP);
    float4* o4 = (float4*)o;       // 784B-aligned

    if (sel < 0) {
        float4 z = make_float4(0.f, 0.f, 0.f, 0.f);
        for (int i = tid; i < CPB * 49; i += 224) o4[i] = z;
        return;
    }

    int S = (lvl == 0) ? 28 : (lvl == 1) ? 56 : 112;
    int SS = S * S;
    const float* fbase = ((lvl == 0) ? p32 : (lvl == 1) ? p16 : p8)
                         + ((size_t)b * CCH + cg) * (size_t)SS;

    // recompute the scaled cxcywh box from raw inputs (bit-exact vs the
    // reference's scaled concat); fed into roi_align as x1,y1,x2,y2.
    int src = sel >> 11;
    int jj  = sel & 2047;
    const float* bpp = ((src == 0) ? b32 : (src == 1) ? b16 : b8)
                       + ((size_t)(b * 2048 + jj)) * 4;
    float s = (src == 0) ? 32.f : (src == 1) ? 16.f : 8.f;
    float x1 = __fmul_rn(bpp[0], s);
    float y1 = __fmul_rn(bpp[1], s);
    float x2 = __fmul_rn(bpp[2], s);
    float y2 = __fmul_rn(bpp[3], s);
    float bw = __fdiv_rn(__fsub_rn(x2, x1), 14.0f);
    float bh = __fdiv_rn(__fsub_rn(y2, y1), 14.0f);

    float lim = (float)(S - 1);
    bool xc = (x1 >= lim) && (bw >= 0.f);   // all x-samples clamp to S-1, fx=0
    bool yc = (y1 >= lim) && (bh >= 0.f);   // all y-samples clamp to S-1, fy=0

    // ---- corner path: tile == F[c][S*S-1] exactly ----
    if (xc && yc) {
        int c = tid / 14;                 // 224 = 16*14: c in [0,16), r in [0,14)
        int rr = tid - c * 14;
        float v = __ldg(fbase + (size_t)c * SS + (SS - 1));
        float4 v4 = make_float4(v, v, v, v);
        int base = c * 49;
        #pragma unroll
        for (int i = rr; i < 49; i += 14) o4[base + i] = v4;
        return;
    }

    // ---- x-clamped: every row constant; v depends on (c, oy) only ----
    if (xc) {
        int c  = tid / 14;
        int oy = tid - c * 14;
        const float* f = fbase + (size_t)c * SS;
        float acc = 0.f;
        #pragma unroll
        for (int q = 0; q < 2; ++q) {
            float ty = __fadd_rn((float)oy, q ? 0.75f : 0.25f);
            float cy = __fadd_rn(y1, __fmul_rn(ty, bh));
            cy = fminf(fmaxf(cy, 0.0f), lim);
            float c0 = floorf(cy);
            float fy = __fsub_rn(cy, c0);
            int iy0 = (int)c0;
            int iy1 = min(iy0 + 1, S - 1);
            float g0 = __ldg(f + iy0 * S + (S - 1));
            float g1 = __ldg(f + iy1 * S + (S - 1));
            acc += g0 * (1.0f - fy) + g1 * fy;
        }
        float v = acc * 0.5f;             // mean of 4 samples, pairs equal
        float* op = o + c * 196 + oy * 14;
        #pragma unroll
        for (int i = 0; i < 14; ++i) op[i] = v;
        return;
    }

    // ---- y-clamped: every column constant; v depends on (c, ox) only ----
    if (yc) {
        int c  = tid / 14;
        int ox = tid - c * 14;
        const float* f = fbase + (size_t)c * SS + (size_t)(S - 1) * S;  // last row
        float acc = 0.f;
        #pragma unroll
        for (int q = 0; q < 2; ++q) {
            float tx = __fadd_rn((float)ox, q ? 0.75f : 0.25f);
            float cx = __fadd_rn(x1, __fmul_rn(tx, bw));
            cx = fminf(fmaxf(cx, 0.0f), lim);
            float d0 = floorf(cx);
            float fx = __fsub_rn(cx, d0);
            int ix0 = (int)d0;
            int ix1 = min(ix0 + 1, S - 1);
            float g0 = __ldg(f + ix0);
            float g1 = __ldg(f + ix1);
            acc += g0 * (1.0f - fx) + g1 * fx;
        }
        float v = acc * 0.5f;
        float* op = o + c * 196 + ox;
        #pragma unroll
        for (int i = 0; i < 14; ++i) op[i * 14] = v;
        return;
    }

    // ---- full bilinear path ----
    if (tid >= OUTP * OUTP) return;             // 196 active threads

    int p  = tid;
    int oy = p / OUTP;
    int ox = p - oy * OUTP;

    int   iy0[2], iy1[2], ix0[2], ix1[2];
    float fy[2], fx[2];
    #pragma unroll
    for (int q = 0; q < 2; ++q) {
        float ty = __fadd_rn((float)oy, q ? 0.75f : 0.25f);
        float cy = __fadd_rn(y1, __fmul_rn(ty, bh));
        cy = fminf(fmaxf(cy, 0.0f), lim);
        float c0 = floorf(cy);
        fy[q]  = __fsub_rn(cy, c0);
        iy0[q] = (int)c0;
        iy1[q] = min(iy0[q] + 1, S - 1);

        float tx = __fadd_rn((float)ox, q ? 0.75f : 0.25f);
        float cx = __fadd_rn(x1, __fmul_rn(tx, bw));
        cx = fminf(fmaxf(cx, 0.0f), lim);
        float d0 = floorf(cx);
        fx[q]  = __fsub_rn(cx, d0);
        ix0[q] = (int)d0;
        ix1[q] = min(ix0[q] + 1, S - 1);
    }

    // 16 corner offsets + weights (0.25 mean folded in)
    int   off[16];
    float w[16];
    #pragma unroll
    for (int sy = 0; sy < 2; ++sy) {
        #pragma unroll
        for (int sx = 0; sx < 2; ++sx) {
            int s4 = (sy * 2 + sx) * 4;
            int Y0 = iy0[sy] * S, Y1 = iy1[sy] * S;
            float gy = fy[sy], igy = 1.0f - gy;
            float gx = fx[sx], igx = 1.0f - gx;
            off[s4 + 0] = Y0 + ix0[sx];  w[s4 + 0] = igy * igx * 0.25f;
            off[s4 + 1] = Y0 + ix1[sx];  w[s4 + 1] = igy * gx  * 0.25f;
            off[s4 + 2] = Y1 + ix0[sx];  w[s4 + 2] = gy  * igx * 0.25f;
            off[s4 + 3] = Y1 + ix1[sx];  w[s4 + 3] = gy  * gx  * 0.25f;
        }
    }

    const float* f  = fbase;
    float*       op = o + p;
    #pragma unroll 2
    for (int c = 0; c < CPB; ++c) {
        float a0 = 0.f, a1 = 0.f, a2 = 0.f, a3 = 0.f;
        #pragma unroll
        for (int i = 0; i < 4; ++i) {
            a0 = fmaf(__ldg(f + off[4 * i + 0]), w[4 * i + 0], a0);
            a1 = fmaf(__ldg(f + off[4 * i + 1]), w[4 * i + 1], a1);
            a2 = fmaf(__ldg(f + off[4 * i + 2]), w[4 * i + 2], a2);
            a3 = fmaf(__ldg(f + off[4 * i + 3]), w[4 * i + 3], a3);
        }
        *op = (a0 + a1) + (a2 + a3);
        f  += SS;
        op += OUTP * OUTP;
    }
}

// ------------------------------- launcher ------------------------------------
extern "C" void kernel_launch(void* const* d_in, const int* in_sizes, int n_in,
                              void* d_out, int out_size) {
    const float* p32 = (const float*)d_in[0];
    const float* p16 = (const float*)d_in[1];
    const float* p8  = (const float*)d_in[2];
    // d_in[3] = p4 (unused by the reference forward)
    const float* b32 = (const float*)d_in[4];
    const float* b16 = (const float*)d_in[5];
    const float* b8  = (const float*)d_in[6];
    const float* s32 = (const float*)d_in[7];
    const float* s16 = (const float*)d_in[8];
    const float* s8  = (const float*)d_in[9];
    float* out = (float*)d_out;

    // ONE extra stream + TWO events (proven footprint).
    static cudaStream_t sn = nullptr;      // high-priority: nms
    static cudaEvent_t  ev0, ev1;
    if (sn == nullptr) {
        int loPri, hiPri;
        cudaDeviceGetStreamPriorityRange(&loPri, &hiPri);
        cudaStreamCreateWithPriority(&sn, cudaStreamNonBlocking, hiPri);
        cudaEventCreateWithFlags(&ev0, cudaEventDisableTiming);
        cudaEventCreateWithFlags(&ev1, cudaEventDisableTiming);
        // nms: keys (48KB) + boxes (96KB) = 144KB; roi: 96KB fence
        cudaFuncSetAttribute(nms_kernel,
                             cudaFuncAttributeMaxDynamicSharedMemorySize,
                             (int)((size_t)NBOX * (8 + 16)));
        cudaFuncSetAttribute(roi_kernel,
                             cudaFuncAttributeMaxDynamicSharedMemorySize,
                             ROI_SMEM);
    }
    const size_t NMS_SMEM = (size_t)NBOX * (8 + 16);

    // fork: nms(N+1) must wait for ALL of replay N's default-stream work
    // (gate + roi) so re-init of g_sel can't race late roi readers.
    cudaEventRecord(ev0, 0);
    cudaStreamWaitEvent(sn, ev0, 0);

    // nms on the high-priority stream: self-initializes its g_sel row,
    // signals residency, streams selections.
    nms_kernel<<<6, NMS_BD, NMS_SMEM, sn>>>(b32, b16, b8, s32, s16, s8);

    // gate (default stream): returns once all 6 nms blocks are resident
    // (sentinels written), then resets g_ready for the next replay.
    gate_kernel<<<1, 32>>>();

    // roi on the default stream, kk-major order, smem fence
    roi_kernel<<<6144, 224, ROI_SMEM>>>(p32, p16, p8, b32, b16, b8, out);

    // join the nms stream back into the default stream
    cudaEventRecord(ev1, sn);
    cudaStreamWaitEvent(0, ev1, 0);
}